// round 3
// baseline (speedup 1.0000x reference)
#include <cuda_runtime.h>

// ---------------------------------------------------------------------------
// GQA: x->(Q,K,V) projections, causal flash attention (GQA, 32 q-heads over
// 8 kv-heads, d_k=64), output projection. All fp32. Packed f32x2 FMA
// (Blackwell fma.rn.f32x2) used in all inner loops to double fp32 throughput.
// ---------------------------------------------------------------------------

#define D_MODEL 2048
#define KV_DIM  512
#define N_HEADS 32
#define DK      64
#define BATCH   4
#define SEQ     2048
#define MROWS   (BATCH * SEQ)   // 8192

// Scratch (device globals: allocation-free)
__device__ float g_q[MROWS * D_MODEL];   // 64 MB
__device__ float g_k[MROWS * KV_DIM];    // 16 MB
__device__ float g_v[MROWS * KV_DIM];    // 16 MB
__device__ float g_o[MROWS * D_MODEL];   // 64 MB

// ---- packed f32x2 helpers -------------------------------------------------
__device__ __forceinline__ unsigned long long pack2(float lo, float hi) {
    unsigned long long r;
    asm("mov.b64 %0, {%1, %2};" : "=l"(r) : "f"(lo), "f"(hi));
    return r;
}
__device__ __forceinline__ void unpack2(float& lo, float& hi, unsigned long long v) {
    asm("mov.b64 {%0, %1}, %2;" : "=f"(lo), "=f"(hi) : "l"(v));
}
__device__ __forceinline__ unsigned long long fma2(unsigned long long a,
                                                   unsigned long long b,
                                                   unsigned long long c) {
    unsigned long long d;
    asm("fma.rn.f32x2 %0, %1, %2, %3;" : "=l"(d) : "l"(a), "l"(b), "l"(c));
    return d;
}
__device__ __forceinline__ unsigned long long mul2(unsigned long long a,
                                                   unsigned long long b) {
    unsigned long long d;
    asm("mul.rn.f32x2 %0, %1, %2;" : "=l"(d) : "l"(a), "l"(b));
    return d;
}

// ---------------------------------------------------------------------------
// SGEMM + bias:  C[M,N] = A[M,K] @ B[K,N] + bias[N]
// 128x128 block tile, BK=8, 256 threads, 8x8 per thread, f32x2 accumulators.
// All dims here are multiples of the tile sizes (M=8192, N in {2048,512}, K=2048).
// ---------------------------------------------------------------------------
#define BM 128
#define BN 128
#define BKS 8

__global__ void __launch_bounds__(256)
sgemm_bias_kernel(const float* __restrict__ A, const float* __restrict__ B,
                  const float* __restrict__ bias, float* __restrict__ C,
                  int M, int N, int K)
{
    __shared__ __align__(16) float As[BKS * BM];   // k-major, transposed A tile
    __shared__ __align__(16) float Bs[BKS * BN];

    const int tid  = threadIdx.x;
    const int row0 = blockIdx.y * BM;
    const int col0 = blockIdx.x * BN;
    const int ty   = tid >> 4;    // 0..15 -> 8 rows each
    const int tx   = tid & 15;    // 0..15 -> 8 cols each

    const int a_row  = tid >> 1;         // 0..127
    const int a_col4 = (tid & 1) * 4;    // 0 or 4
    const int b_row  = tid >> 5;         // 0..7
    const int b_col4 = (tid & 31) * 4;   // 0..124

    const float* Ap = A + (long long)(row0 + a_row) * K + a_col4;
    const float* Bp = B + (long long)b_row * N + col0 + b_col4;

    unsigned long long c2[8][4];
#pragma unroll
    for (int i = 0; i < 8; i++)
#pragma unroll
        for (int j = 0; j < 4; j++) c2[i][j] = 0ULL;

    for (int k0 = 0; k0 < K; k0 += BKS) {
        float4 a4 = *(const float4*)(Ap + k0);
        float4 b4 = *(const float4*)(Bp + (long long)k0 * N);
        __syncthreads();
        As[(a_col4 + 0) * BM + a_row] = a4.x;
        As[(a_col4 + 1) * BM + a_row] = a4.y;
        As[(a_col4 + 2) * BM + a_row] = a4.z;
        As[(a_col4 + 3) * BM + a_row] = a4.w;
        *(float4*)(Bs + b_row * BN + b_col4) = b4;
        __syncthreads();
#pragma unroll
        for (int k = 0; k < BKS; k++) {
            float4 a0 = *(const float4*)(As + k * BM + ty * 8);
            float4 a1 = *(const float4*)(As + k * BM + ty * 8 + 4);
            ulonglong2 bb0 = *(const ulonglong2*)(Bs + k * BN + tx * 8);
            ulonglong2 bb1 = *(const ulonglong2*)(Bs + k * BN + tx * 8 + 4);
            float av[8] = {a0.x, a0.y, a0.z, a0.w, a1.x, a1.y, a1.z, a1.w};
#pragma unroll
            for (int i = 0; i < 8; i++) {
                unsigned long long ai = pack2(av[i], av[i]);
                c2[i][0] = fma2(ai, bb0.x, c2[i][0]);
                c2[i][1] = fma2(ai, bb0.y, c2[i][1]);
                c2[i][2] = fma2(ai, bb1.x, c2[i][2]);
                c2[i][3] = fma2(ai, bb1.y, c2[i][3]);
            }
        }
    }

    float bv[8];
#pragma unroll
    for (int j = 0; j < 8; j++) bv[j] = bias[col0 + tx * 8 + j];
#pragma unroll
    for (int i = 0; i < 8; i++) {
        int row = row0 + ty * 8 + i;
        float c[8];
        unpack2(c[0], c[1], c2[i][0]);
        unpack2(c[2], c[3], c2[i][1]);
        unpack2(c[4], c[5], c2[i][2]);
        unpack2(c[6], c[7], c2[i][3]);
        float* Cp = C + (long long)row * N + col0 + tx * 8;
        float4 r0 = make_float4(c[0] + bv[0], c[1] + bv[1], c[2] + bv[2], c[3] + bv[3]);
        float4 r1 = make_float4(c[4] + bv[4], c[5] + bv[5], c[6] + bv[6], c[7] + bv[7]);
        *(float4*)Cp = r0;
        *(float4*)(Cp + 4) = r1;
    }
}

// ---------------------------------------------------------------------------
// Causal flash attention. One block = (batch b, q-head h, 64 query rows).
// BR=BC=64, D=64. 256 threads as 16x16; each thread owns a 4x4 microtile:
// rows ty*4+i (fixed across phases), S-cols / O-cols tx*4+jj.
// Q and K stored d-major (transposed) in smem -> conflict-free float4 LDS.
// Online softmax with per-row (m,l) replicated across the 16 tx lanes via shfl.
// Accumulators packed f32x2.
// ---------------------------------------------------------------------------
__global__ void __launch_bounds__(256)
flash_kernel()
{
    extern __shared__ float sm[];
    float* sQT = sm;             // [64 d][64 r]
    float* sKT = sm + 4096;      // [64 d][64 j]
    float* sV  = sm + 8192;      // [64 j][64 c]
    float* sP  = sm + 12288;     // [64 r][65]   (padded)

    const int tid = threadIdx.x;
    const int ty = tid >> 4;     // 0..15
    const int tx = tid & 15;     // 0..15
    const int b  = blockIdx.z;
    const int h  = blockIdx.y;
    const int qi = (int)gridDim.x - 1 - (int)blockIdx.x;  // heavy tiles first
    const int q0 = qi * 64;
    const int kvh = h >> 2;

    const float* qbase = g_q + (long long)(b * SEQ) * D_MODEL + h * DK;
    const float* kbase = g_k + (long long)(b * SEQ) * KV_DIM + kvh * DK;
    const float* vbase = g_v + (long long)(b * SEQ) * KV_DIM + kvh * DK;

    // Load Q tile transposed (once per block)
#pragma unroll
    for (int e = 0; e < 4; e++) {
        int lin = e * 256 + tid;
        int r = lin >> 4;
        int d4 = (lin & 15) * 4;
        float4 t4 = *(const float4*)(qbase + (long long)(q0 + r) * D_MODEL + d4);
        sQT[(d4 + 0) * 64 + r] = t4.x;
        sQT[(d4 + 1) * 64 + r] = t4.y;
        sQT[(d4 + 2) * 64 + r] = t4.z;
        sQT[(d4 + 3) * 64 + r] = t4.w;
    }

    unsigned long long o2[4][2];
    float m[4], l[4];
#pragma unroll
    for (int i = 0; i < 4; i++) {
        o2[i][0] = 0ULL; o2[i][1] = 0ULL;
        m[i] = -1e30f; l[i] = 0.0f;
    }

    for (int t = 0; t <= qi; t++) {
        const int j0 = t * 64;

        // Stage K/V tile through registers to overlap with the barrier
        float4 kreg[4], vreg[4];
#pragma unroll
        for (int e = 0; e < 4; e++) {
            int lin = e * 256 + tid;
            int r = lin >> 4;
            int d4 = (lin & 15) * 4;
            kreg[e] = *(const float4*)(kbase + (long long)(j0 + r) * KV_DIM + d4);
            vreg[e] = *(const float4*)(vbase + (long long)(j0 + r) * KV_DIM + d4);
        }
        __syncthreads();   // previous tile's smem reads complete
#pragma unroll
        for (int e = 0; e < 4; e++) {
            int lin = e * 256 + tid;
            int r = lin >> 4;
            int d4 = (lin & 15) * 4;
            sKT[(d4 + 0) * 64 + r] = kreg[e].x;
            sKT[(d4 + 1) * 64 + r] = kreg[e].y;
            sKT[(d4 + 2) * 64 + r] = kreg[e].z;
            sKT[(d4 + 3) * 64 + r] = kreg[e].w;
            *(float4*)(sV + r * 64 + d4) = vreg[e];
        }
        __syncthreads();

        // ---- S = Q @ K^T (4x4 per thread, packed pairs along j) ----
        unsigned long long s2[4][2];
#pragma unroll
        for (int i = 0; i < 4; i++) { s2[i][0] = 0ULL; s2[i][1] = 0ULL; }
#pragma unroll 16
        for (int d = 0; d < 64; d++) {
            float4 qa = *(const float4*)(sQT + d * 64 + ty * 4);
            ulonglong2 kb = *(const ulonglong2*)(sKT + d * 64 + tx * 4);
            unsigned long long q0p = pack2(qa.x, qa.x);
            unsigned long long q1p = pack2(qa.y, qa.y);
            unsigned long long q2p = pack2(qa.z, qa.z);
            unsigned long long q3p = pack2(qa.w, qa.w);
            s2[0][0] = fma2(q0p, kb.x, s2[0][0]);
            s2[0][1] = fma2(q0p, kb.y, s2[0][1]);
            s2[1][0] = fma2(q1p, kb.x, s2[1][0]);
            s2[1][1] = fma2(q1p, kb.y, s2[1][1]);
            s2[2][0] = fma2(q2p, kb.x, s2[2][0]);
            s2[2][1] = fma2(q2p, kb.y, s2[2][1]);
            s2[3][0] = fma2(q3p, kb.x, s2[3][0]);
            s2[3][1] = fma2(q3p, kb.y, s2[3][1]);
        }

        float s[4][4];
        const float scale = 0.125f;   // 1/sqrt(64)
#pragma unroll
        for (int i = 0; i < 4; i++) {
            unpack2(s[i][0], s[i][1], s2[i][0]);
            unpack2(s[i][2], s[i][3], s2[i][1]);
#pragma unroll
            for (int jj = 0; jj < 4; jj++) s[i][jj] *= scale;
        }

        if (t == qi) {  // diagonal tile: causal mask (j_local > r_local)
#pragma unroll
            for (int i = 0; i < 4; i++)
#pragma unroll
                for (int jj = 0; jj < 4; jj++)
                    if (tx * 4 + jj > ty * 4 + i) s[i][jj] = -1e30f;
        }

        // ---- online softmax per row (replicated across the 16 tx lanes) ----
#pragma unroll
        for (int i = 0; i < 4; i++) {
            float mx = fmaxf(fmaxf(s[i][0], s[i][1]), fmaxf(s[i][2], s[i][3]));
#pragma unroll
            for (int off = 8; off; off >>= 1)
                mx = fmaxf(mx, __shfl_xor_sync(0xffffffffu, mx, off));
            float mn = fmaxf(m[i], mx);
            float alpha = __expf(m[i] - mn);
            m[i] = mn;
            float p0 = __expf(s[i][0] - mn);
            float p1 = __expf(s[i][1] - mn);
            float p2 = __expf(s[i][2] - mn);
            float p3 = __expf(s[i][3] - mn);
            float rs = (p0 + p1) + (p2 + p3);
#pragma unroll
            for (int off = 8; off; off >>= 1)
                rs += __shfl_xor_sync(0xffffffffu, rs, off);
            l[i] = l[i] * alpha + rs;
            unsigned long long al2 = pack2(alpha, alpha);
            o2[i][0] = mul2(o2[i][0], al2);
            o2[i][1] = mul2(o2[i][1], al2);
            float* pr = sP + (ty * 4 + i) * 65 + tx * 4;
            pr[0] = p0; pr[1] = p1; pr[2] = p2; pr[3] = p3;
        }
        __syncwarp();  // sP rows produced & consumed within the same warp

        // ---- O += P @ V ----
#pragma unroll 16
        for (int j = 0; j < 64; j++) {
            ulonglong2 vv = *(const ulonglong2*)(sV + j * 64 + tx * 4);
#pragma unroll
            for (int i = 0; i < 4; i++) {
                float p = sP[(ty * 4 + i) * 65 + j];
                unsigned long long pp = pack2(p, p);
                o2[i][0] = fma2(pp, vv.x, o2[i][0]);
                o2[i][1] = fma2(pp, vv.y, o2[i][1]);
            }
        }
    }

    // ---- epilogue: normalize, write o in (B,S,heads*dk) layout ----
    float* obase = g_o + (long long)(b * SEQ) * D_MODEL + h * DK;
#pragma unroll
    for (int i = 0; i < 4; i++) {
        float inv = __fdividef(1.0f, l[i]);
        float a0, a1, a2, a3;
        unpack2(a0, a1, o2[i][0]);
        unpack2(a2, a3, o2[i][1]);
        float4 r = make_float4(a0 * inv, a1 * inv, a2 * inv, a3 * inv);
        *(float4*)(obase + (long long)(q0 + ty * 4 + i) * D_MODEL + tx * 4) = r;
    }
}

// ---------------------------------------------------------------------------
// Launch: 3 projection GEMMs -> flash attention -> output GEMM (into d_out).
// All launches on the default capture stream; no syncs, no allocations.
// ---------------------------------------------------------------------------
extern "C" void kernel_launch(void* const* d_in, const int* in_sizes, int n_in,
                              void* d_out, int out_size)
{
    const float* x  = (const float*)d_in[0];
    const float* Wq = (const float*)d_in[1];
    const float* bq = (const float*)d_in[2];
    const float* Wk = (const float*)d_in[3];
    const float* bk = (const float*)d_in[4];
    const float* Wv = (const float*)d_in[5];
    const float* bv = (const float*)d_in[6];
    const float* Wo = (const float*)d_in[7];
    const float* bo = (const float*)d_in[8];
    float* out = (float*)d_out;

    float *qp, *kp, *vp, *op;
    cudaGetSymbolAddress((void**)&qp, g_q);
    cudaGetSymbolAddress((void**)&kp, g_k);
    cudaGetSymbolAddress((void**)&vp, g_v);
    cudaGetSymbolAddress((void**)&op, g_o);

    const int flash_smem = (4096 * 3 + 64 * 65) * (int)sizeof(float);  // 65792 B
    cudaFuncSetAttribute((const void*)flash_kernel,
                         cudaFuncAttributeMaxDynamicSharedMemorySize, flash_smem);

    dim3 blk(256);
    sgemm_bias_kernel<<<dim3(D_MODEL / BN, MROWS / BM), blk>>>(
        x, Wq, bq, qp, MROWS, D_MODEL, D_MODEL);
    sgemm_bias_kernel<<<dim3(KV_DIM / BN, MROWS / BM), blk>>>(
        x, Wk, bk, kp, MROWS, KV_DIM, D_MODEL);
    sgemm_bias_kernel<<<dim3(KV_DIM / BN, MROWS / BM), blk>>>(
        x, Wv, bv, vp, MROWS, KV_DIM, D_MODEL);
    flash_kernel<<<dim3(SEQ / 64, N_HEADS, BATCH), blk, flash_smem>>>();
    sgemm_bias_kernel<<<dim3(D_MODEL / BN, MROWS / BM), blk>>>(
        op, Wo, bo, out, MROWS, D_MODEL, D_MODEL);
}

// round 5
// speedup vs baseline: 1.5851x; 1.5851x over previous
#include <cuda_runtime.h>
#include <cuda_bf16.h>
#include <cstdint>

// ---------------------------------------------------------------------------
// GQA fp32. GEMMs via legacy tensor-core path (mma.sync bf16, hi/lo split,
// 3 MMAs per term) since the harness ptxas target is plain sm_103 (no 'a'
// features => no tcgen05). Flash attention stays fp32 f32x2.
// ---------------------------------------------------------------------------

#define D_MODEL 2048
#define KV_DIM  512
#define N_HEADS 32
#define DK      64
#define BATCH   4
#define SEQ     2048
#define MROWS   (BATCH * SEQ)   // 8192

// Scratch (device globals: allocation-free)
__device__ float g_q[MROWS * D_MODEL];
__device__ float g_k[MROWS * KV_DIM];
__device__ float g_v[MROWS * KV_DIM];
// x and attention-output, pre-split to bf16 hi/lo (row-major [M][K])
__device__ __nv_bfloat16 g_xh[MROWS * D_MODEL];
__device__ __nv_bfloat16 g_xl[MROWS * D_MODEL];
__device__ __nv_bfloat16 g_oh[MROWS * D_MODEL];
__device__ __nv_bfloat16 g_ol[MROWS * D_MODEL];
// Pre-transposed, hi/lo-split weights: W^T[n][k] bf16
__device__ __nv_bfloat16 g_wqt_h[D_MODEL * D_MODEL];
__device__ __nv_bfloat16 g_wqt_l[D_MODEL * D_MODEL];
__device__ __nv_bfloat16 g_wkt_h[KV_DIM * D_MODEL];
__device__ __nv_bfloat16 g_wkt_l[KV_DIM * D_MODEL];
__device__ __nv_bfloat16 g_wvt_h[KV_DIM * D_MODEL];
__device__ __nv_bfloat16 g_wvt_l[KV_DIM * D_MODEL];
__device__ __nv_bfloat16 g_wot_h[D_MODEL * D_MODEL];
__device__ __nv_bfloat16 g_wot_l[D_MODEL * D_MODEL];

// ==================== helpers ====================
__device__ __forceinline__ uint32_t smem_u32(const void* p) {
    uint32_t a;
    asm("{ .reg .u64 t; cvta.to.shared.u64 t, %1; cvt.u32.u64 %0, t; }" : "=r"(a) : "l"(p));
    return a;
}
__device__ __forceinline__ void cp16(uint32_t dst, const void* src) {
    asm volatile("cp.async.cg.shared.global [%0], [%1], 16;" :: "r"(dst), "l"(src));
}
#define CP_COMMIT() asm volatile("cp.async.commit_group;" ::: "memory")
#define CP_WAIT(n)  asm volatile("cp.async.wait_group %0;" :: "n"(n) : "memory")

__device__ __forceinline__ void ldm_x4(uint32_t* r, uint32_t addr) {
    asm volatile("ldmatrix.sync.aligned.m8n8.x4.shared.b16 {%0,%1,%2,%3}, [%4];"
        : "=r"(r[0]), "=r"(r[1]), "=r"(r[2]), "=r"(r[3]) : "r"(addr) : "memory");
}
__device__ __forceinline__ void ldm_x2(uint32_t* r, uint32_t addr) {
    asm volatile("ldmatrix.sync.aligned.m8n8.x2.shared.b16 {%0,%1}, [%2];"
        : "=r"(r[0]), "=r"(r[1]) : "r"(addr) : "memory");
}
__device__ __forceinline__ void mma16816(float* d, const uint32_t* a, const uint32_t* b) {
    asm volatile("mma.sync.aligned.m16n8k16.row.col.f32.bf16.bf16.f32 "
        "{%0,%1,%2,%3}, {%4,%5,%6,%7}, {%8,%9}, {%0,%1,%2,%3};"
        : "+f"(d[0]), "+f"(d[1]), "+f"(d[2]), "+f"(d[3])
        : "r"(a[0]), "r"(a[1]), "r"(a[2]), "r"(a[3]), "r"(b[0]), "r"(b[1]));
}
__device__ __forceinline__ uint32_t bfpack(__nv_bfloat16 a, __nv_bfloat16 b) {
    return (uint32_t)__bfloat16_as_ushort(a) | ((uint32_t)__bfloat16_as_ushort(b) << 16);
}

// ==================== x / o split: fp32 -> bf16 hi + bf16 lo ====================
__global__ void __launch_bounds__(256)
split_kernel(const float* __restrict__ X, __nv_bfloat16* __restrict__ H,
             __nv_bfloat16* __restrict__ L, int n4)
{
    int i = blockIdx.x * 256 + threadIdx.x;
    if (i >= n4) return;
    float4 v = ((const float4*)X)[i];
    __nv_bfloat16 h0 = __float2bfloat16(v.x), h1 = __float2bfloat16(v.y);
    __nv_bfloat16 h2 = __float2bfloat16(v.z), h3 = __float2bfloat16(v.w);
    __nv_bfloat16 l0 = __float2bfloat16(v.x - __bfloat162float(h0));
    __nv_bfloat16 l1 = __float2bfloat16(v.y - __bfloat162float(h1));
    __nv_bfloat16 l2 = __float2bfloat16(v.z - __bfloat162float(h2));
    __nv_bfloat16 l3 = __float2bfloat16(v.w - __bfloat162float(h3));
    ((uint2*)H)[i] = make_uint2(bfpack(h0, h1), bfpack(h2, h3));
    ((uint2*)L)[i] = make_uint2(bfpack(l0, l1), bfpack(l2, l3));
}

// ==================== weight transpose + split ====================
// W: [Kd][Nd] fp32 row-major -> Th/Tl: [Nd][Kd] bf16
__global__ void __launch_bounds__(256)
transpose_split_kernel(const float* __restrict__ W, __nv_bfloat16* __restrict__ Th,
                       __nv_bfloat16* __restrict__ Tl, int Kd, int Nd)
{
    __shared__ float tile[32][33];
    const int tx = threadIdx.x, ty = threadIdx.y;
    const int n0 = blockIdx.x * 32, k0 = blockIdx.y * 32;
#pragma unroll
    for (int j = ty; j < 32; j += 8)
        tile[j][tx] = W[(size_t)(k0 + j) * Nd + n0 + tx];
    __syncthreads();
#pragma unroll
    for (int j = ty; j < 32; j += 8) {
        float v = tile[tx][j];                 // = W[k0+tx][n0+j]
        __nv_bfloat16 h = __float2bfloat16(v);
        __nv_bfloat16 lo = __float2bfloat16(v - __bfloat162float(h));
        Th[(size_t)(n0 + j) * Kd + k0 + tx] = h;
        Tl[(size_t)(n0 + j) * Kd + k0 + tx] = lo;
    }
}

// ==================== mma.sync bf16-split GEMM ====================
// C[M,N] = (Ah+Al)[M,K] @ (Bh+Bl)^T[N,K] + bias  (drop Al*Bl)
// CTA 128x128, BK=32, 8 warps of 64x32, cp.async 2-stage, padded-row smem.
#define ROWB 80                       // smem bytes per 32-bf16 row (64B + 16B pad)
#define TILEB (128 * ROWB)            // 10240 B per operand tile
#define STAGEB (4 * TILEB)            // Ah,Al,Bh,Bl per stage = 40960 B
#define GSMEM (2 * STAGEB)            // 81920 B

__global__ void __launch_bounds__(256, 1)
gemm_mma_kernel(const __nv_bfloat16* __restrict__ Ah, const __nv_bfloat16* __restrict__ Al,
                const __nv_bfloat16* __restrict__ Bh, const __nv_bfloat16* __restrict__ Bl,
                const float* __restrict__ bias, float* __restrict__ C,
                int M, int N, int K)
{
    extern __shared__ __align__(16) char smem[];
    const uint32_t sb = smem_u32(smem);
    const int tid = threadIdx.x;
    const int lane = tid & 31, w = tid >> 5;
    const int wr = w >> 2, wc = w & 3;               // warp grid 2x4
    const int row0 = blockIdx.y * 128, col0 = blockIdx.x * 128;
    const int nc = K >> 5;                            // 32-wide K chunks

    const __nv_bfloat16* srcs[4] = {
        Ah + (size_t)row0 * K, Al + (size_t)row0 * K,
        Bh + (size_t)col0 * K, Bl + (size_t)col0 * K };

    auto load_stage = [&](int kc, int st) {
        uint32_t stb = sb + st * STAGEB;
#pragma unroll
        for (int arr = 0; arr < 4; arr++) {
            const __nv_bfloat16* s = srcs[arr];
            uint32_t base = stb + arr * TILEB;
#pragma unroll
            for (int i = 0; i < 2; i++) {
                int chunk = tid + i * 256;           // 0..511
                int r = chunk >> 2, kq = chunk & 3;  // row, 16B quarter
                cp16(base + r * ROWB + kq * 16,
                     s + (size_t)r * K + kc * 32 + kq * 8);
            }
        }
    };

    float d[4][4][4];
#pragma unroll
    for (int mf = 0; mf < 4; mf++)
#pragma unroll
        for (int nf = 0; nf < 4; nf++)
#pragma unroll
            for (int e = 0; e < 4; e++) d[mf][nf][e] = 0.0f;

    load_stage(0, 0);
    CP_COMMIT();

    const uint32_t a_lane_off = (lane & 15) * ROWB + (lane >> 4) * 16;
    const uint32_t b_lane_off = (lane & 7) * ROWB + ((lane >> 3) & 1) * 16;

    for (int kc = 0; kc < nc; kc++) {
        const int st = kc & 1;
        if (kc + 1 < nc) { load_stage(kc + 1, st ^ 1); CP_COMMIT(); CP_WAIT(1); }
        else            { CP_WAIT(0); }
        __syncthreads();

        const uint32_t aH = sb + st * STAGEB + 0 * TILEB + wr * 64 * ROWB + a_lane_off;
        const uint32_t aL = sb + st * STAGEB + 1 * TILEB + wr * 64 * ROWB + a_lane_off;
        const uint32_t bH = sb + st * STAGEB + 2 * TILEB + wc * 32 * ROWB + b_lane_off;
        const uint32_t bL = sb + st * STAGEB + 3 * TILEB + wc * 32 * ROWB + b_lane_off;

#pragma unroll
        for (int ks = 0; ks < 2; ks++) {
            const uint32_t ko = ks * 32;             // 16 bf16 = 32 bytes
            uint32_t ah[4][4], al[4][4], bh[4][2], bl[4][2];
#pragma unroll
            for (int mf = 0; mf < 4; mf++) {
                ldm_x4(ah[mf], aH + mf * 16 * ROWB + ko);
                ldm_x4(al[mf], aL + mf * 16 * ROWB + ko);
            }
#pragma unroll
            for (int nf = 0; nf < 4; nf++) {
                ldm_x2(bh[nf], bH + nf * 8 * ROWB + ko);
                ldm_x2(bl[nf], bL + nf * 8 * ROWB + ko);
            }
#pragma unroll
            for (int mf = 0; mf < 4; mf++)
#pragma unroll
                for (int nf = 0; nf < 4; nf++) {
                    mma16816(d[mf][nf], ah[mf], bh[nf]);
                    mma16816(d[mf][nf], ah[mf], bl[nf]);
                    mma16816(d[mf][nf], al[mf], bh[nf]);
                }
        }
        __syncthreads();
    }

    // epilogue
#pragma unroll
    for (int mf = 0; mf < 4; mf++) {
        const int r = row0 + wr * 64 + mf * 16 + (lane >> 2);
#pragma unroll
        for (int nf = 0; nf < 4; nf++) {
            const int c = col0 + wc * 32 + nf * 8 + (lane & 3) * 2;
            const float b0 = bias[c], b1 = bias[c + 1];
            *(float2*)(C + (size_t)r * N + c) =
                make_float2(d[mf][nf][0] + b0, d[mf][nf][1] + b1);
            *(float2*)(C + (size_t)(r + 8) * N + c) =
                make_float2(d[mf][nf][2] + b0, d[mf][nf][3] + b1);
        }
    }
}

// ==================== fp32 flash attention (f32x2) ====================
__device__ __forceinline__ unsigned long long pack2(float lo, float hi) {
    unsigned long long r;
    asm("mov.b64 %0, {%1, %2};" : "=l"(r) : "f"(lo), "f"(hi));
    return r;
}
__device__ __forceinline__ void unpack2(float& lo, float& hi, unsigned long long v) {
    asm("mov.b64 {%0, %1}, %2;" : "=f"(lo), "=f"(hi) : "l"(v));
}
__device__ __forceinline__ unsigned long long fma2(unsigned long long a,
                                                   unsigned long long b,
                                                   unsigned long long c) {
    unsigned long long d;
    asm("fma.rn.f32x2 %0, %1, %2, %3;" : "=l"(d) : "l"(a), "l"(b), "l"(c));
    return d;
}
__device__ __forceinline__ unsigned long long mul2(unsigned long long a,
                                                   unsigned long long b) {
    unsigned long long d;
    asm("mul.rn.f32x2 %0, %1, %2;" : "=l"(d) : "l"(a), "l"(b));
    return d;
}

__global__ void __launch_bounds__(256)
flash_kernel()
{
    extern __shared__ float sm[];
    float* sQT = sm;             // [64 d][64 r]
    float* sKT = sm + 4096;      // [64 d][64 j]
    float* sV  = sm + 8192;      // [64 j][64 c]
    float* sP  = sm + 12288;     // [64 r][65]

    const int tid = threadIdx.x;
    const int ty = tid >> 4;
    const int tx = tid & 15;
    const int b  = blockIdx.z;
    const int h  = blockIdx.y;
    const int qi = (int)gridDim.x - 1 - (int)blockIdx.x;
    const int q0 = qi * 64;
    const int kvh = h >> 2;

    const float* qbase = g_q + (long long)(b * SEQ) * D_MODEL + h * DK;
    const float* kbase = g_k + (long long)(b * SEQ) * KV_DIM + kvh * DK;
    const float* vbase = g_v + (long long)(b * SEQ) * KV_DIM + kvh * DK;

#pragma unroll
    for (int e = 0; e < 4; e++) {
        int lin = e * 256 + tid;
        int r = lin >> 4;
        int d4 = (lin & 15) * 4;
        float4 t4 = *(const float4*)(qbase + (long long)(q0 + r) * D_MODEL + d4);
        sQT[(d4 + 0) * 64 + r] = t4.x;
        sQT[(d4 + 1) * 64 + r] = t4.y;
        sQT[(d4 + 2) * 64 + r] = t4.z;
        sQT[(d4 + 3) * 64 + r] = t4.w;
    }

    unsigned long long o2[4][2];
    float m[4], l[4];
#pragma unroll
    for (int i = 0; i < 4; i++) {
        o2[i][0] = 0ULL; o2[i][1] = 0ULL;
        m[i] = -1e30f; l[i] = 0.0f;
    }

    for (int t = 0; t <= qi; t++) {
        const int j0 = t * 64;
        float4 kreg[4], vreg[4];
#pragma unroll
        for (int e = 0; e < 4; e++) {
            int lin = e * 256 + tid;
            int r = lin >> 4;
            int d4 = (lin & 15) * 4;
            kreg[e] = *(const float4*)(kbase + (long long)(j0 + r) * KV_DIM + d4);
            vreg[e] = *(const float4*)(vbase + (long long)(j0 + r) * KV_DIM + d4);
        }
        __syncthreads();
#pragma unroll
        for (int e = 0; e < 4; e++) {
            int lin = e * 256 + tid;
            int r = lin >> 4;
            int d4 = (lin & 15) * 4;
            sKT[(d4 + 0) * 64 + r] = kreg[e].x;
            sKT[(d4 + 1) * 64 + r] = kreg[e].y;
            sKT[(d4 + 2) * 64 + r] = kreg[e].z;
            sKT[(d4 + 3) * 64 + r] = kreg[e].w;
            *(float4*)(sV + r * 64 + d4) = vreg[e];
        }
        __syncthreads();

        unsigned long long s2[4][2];
#pragma unroll
        for (int i = 0; i < 4; i++) { s2[i][0] = 0ULL; s2[i][1] = 0ULL; }
#pragma unroll 16
        for (int d = 0; d < 64; d++) {
            float4 qa = *(const float4*)(sQT + d * 64 + ty * 4);
            ulonglong2 kb = *(const ulonglong2*)(sKT + d * 64 + tx * 4);
            unsigned long long q0p = pack2(qa.x, qa.x);
            unsigned long long q1p = pack2(qa.y, qa.y);
            unsigned long long q2p = pack2(qa.z, qa.z);
            unsigned long long q3p = pack2(qa.w, qa.w);
            s2[0][0] = fma2(q0p, kb.x, s2[0][0]);
            s2[0][1] = fma2(q0p, kb.y, s2[0][1]);
            s2[1][0] = fma2(q1p, kb.x, s2[1][0]);
            s2[1][1] = fma2(q1p, kb.y, s2[1][1]);
            s2[2][0] = fma2(q2p, kb.x, s2[2][0]);
            s2[2][1] = fma2(q2p, kb.y, s2[2][1]);
            s2[3][0] = fma2(q3p, kb.x, s2[3][0]);
            s2[3][1] = fma2(q3p, kb.y, s2[3][1]);
        }

        float s[4][4];
        const float scale = 0.125f;
#pragma unroll
        for (int i = 0; i < 4; i++) {
            unpack2(s[i][0], s[i][1], s2[i][0]);
            unpack2(s[i][2], s[i][3], s2[i][1]);
#pragma unroll
            for (int jj = 0; jj < 4; jj++) s[i][jj] *= scale;
        }

        if (t == qi) {
#pragma unroll
            for (int i = 0; i < 4; i++)
#pragma unroll
                for (int jj = 0; jj < 4; jj++)
                    if (tx * 4 + jj > ty * 4 + i) s[i][jj] = -1e30f;
        }

#pragma unroll
        for (int i = 0; i < 4; i++) {
            float mx = fmaxf(fmaxf(s[i][0], s[i][1]), fmaxf(s[i][2], s[i][3]));
#pragma unroll
            for (int off = 8; off; off >>= 1)
                mx = fmaxf(mx, __shfl_xor_sync(0xffffffffu, mx, off));
            float mn = fmaxf(m[i], mx);
            float alpha = __expf(m[i] - mn);
            m[i] = mn;
            float p0 = __expf(s[i][0] - mn);
            float p1 = __expf(s[i][1] - mn);
            float p2 = __expf(s[i][2] - mn);
            float p3 = __expf(s[i][3] - mn);
            float rs = (p0 + p1) + (p2 + p3);
#pragma unroll
            for (int off = 8; off; off >>= 1)
                rs += __shfl_xor_sync(0xffffffffu, rs, off);
            l[i] = l[i] * alpha + rs;
            unsigned long long al2 = pack2(alpha, alpha);
            o2[i][0] = mul2(o2[i][0], al2);
            o2[i][1] = mul2(o2[i][1], al2);
            float* pr = sP + (ty * 4 + i) * 65 + tx * 4;
            pr[0] = p0; pr[1] = p1; pr[2] = p2; pr[3] = p3;
        }
        __syncwarp();

#pragma unroll 16
        for (int j = 0; j < 64; j++) {
            ulonglong2 vv = *(const ulonglong2*)(sV + j * 64 + tx * 4);
#pragma unroll
            for (int i = 0; i < 4; i++) {
                float p = sP[(ty * 4 + i) * 65 + j];
                unsigned long long pp = pack2(p, p);
                o2[i][0] = fma2(pp, vv.x, o2[i][0]);
                o2[i][1] = fma2(pp, vv.y, o2[i][1]);
            }
        }
    }

    // epilogue: normalize, emit bf16 hi/lo split directly (feeds the Wo GEMM)
    const long long obase = (long long)(b * SEQ) * D_MODEL + h * DK;
#pragma unroll
    for (int i = 0; i < 4; i++) {
        float inv = __fdividef(1.0f, l[i]);
        float a0, a1, a2, a3;
        unpack2(a0, a1, o2[i][0]);
        unpack2(a2, a3, o2[i][1]);
        a0 *= inv; a1 *= inv; a2 *= inv; a3 *= inv;
        __nv_bfloat16 h0 = __float2bfloat16(a0), h1 = __float2bfloat16(a1);
        __nv_bfloat16 h2 = __float2bfloat16(a2), h3 = __float2bfloat16(a3);
        __nv_bfloat16 l0 = __float2bfloat16(a0 - __bfloat162float(h0));
        __nv_bfloat16 l1 = __float2bfloat16(a1 - __bfloat162float(h1));
        __nv_bfloat16 l2 = __float2bfloat16(a2 - __bfloat162float(h2));
        __nv_bfloat16 l3 = __float2bfloat16(a3 - __bfloat162float(h3));
        long long idx = obase + (long long)(q0 + ty * 4 + i) * D_MODEL + tx * 4;
        *(uint2*)(g_oh + idx) = make_uint2(bfpack(h0, h1), bfpack(h2, h3));
        *(uint2*)(g_ol + idx) = make_uint2(bfpack(l0, l1), bfpack(l2, l3));
    }
}

// ==================== launch ====================
extern "C" void kernel_launch(void* const* d_in, const int* in_sizes, int n_in,
                              void* d_out, int out_size)
{
    const float* x  = (const float*)d_in[0];
    const float* Wq = (const float*)d_in[1];
    const float* bq = (const float*)d_in[2];
    const float* Wk = (const float*)d_in[3];
    const float* bk = (const float*)d_in[4];
    const float* Wv = (const float*)d_in[5];
    const float* bv = (const float*)d_in[6];
    const float* Wo = (const float*)d_in[7];
    const float* bo = (const float*)d_in[8];
    float* out = (float*)d_out;

    float *qp, *kp, *vp;
    cudaGetSymbolAddress((void**)&qp, g_q);
    cudaGetSymbolAddress((void**)&kp, g_k);
    cudaGetSymbolAddress((void**)&vp, g_v);
    __nv_bfloat16 *xh, *xl, *oh, *ol;
    cudaGetSymbolAddress((void**)&xh, g_xh);
    cudaGetSymbolAddress((void**)&xl, g_xl);
    cudaGetSymbolAddress((void**)&oh, g_oh);
    cudaGetSymbolAddress((void**)&ol, g_ol);
    __nv_bfloat16 *wqh, *wql, *wkh, *wkl, *wvh, *wvl, *woh, *wol;
    cudaGetSymbolAddress((void**)&wqh, g_wqt_h);
    cudaGetSymbolAddress((void**)&wql, g_wqt_l);
    cudaGetSymbolAddress((void**)&wkh, g_wkt_h);
    cudaGetSymbolAddress((void**)&wkl, g_wkt_l);
    cudaGetSymbolAddress((void**)&wvh, g_wvt_h);
    cudaGetSymbolAddress((void**)&wvl, g_wvt_l);
    cudaGetSymbolAddress((void**)&woh, g_wot_h);
    cudaGetSymbolAddress((void**)&wol, g_wot_l);

    const int flash_smem = (4096 * 3 + 64 * 65) * (int)sizeof(float);  // 65792 B
    cudaFuncSetAttribute((const void*)flash_kernel,
                         cudaFuncAttributeMaxDynamicSharedMemorySize, flash_smem);
    cudaFuncSetAttribute((const void*)gemm_mma_kernel,
                         cudaFuncAttributeMaxDynamicSharedMemorySize, GSMEM);

    // 1) split activations, transpose+split weights
    const int n4 = MROWS * D_MODEL / 4;
    split_kernel<<<(n4 + 255) / 256, 256>>>(x, xh, xl, n4);
    dim3 tb(32, 8);
    transpose_split_kernel<<<dim3(D_MODEL / 32, D_MODEL / 32), tb>>>(Wq, wqh, wql, D_MODEL, D_MODEL);
    transpose_split_kernel<<<dim3(KV_DIM  / 32, D_MODEL / 32), tb>>>(Wk, wkh, wkl, D_MODEL, KV_DIM);
    transpose_split_kernel<<<dim3(KV_DIM  / 32, D_MODEL / 32), tb>>>(Wv, wvh, wvl, D_MODEL, KV_DIM);
    transpose_split_kernel<<<dim3(D_MODEL / 32, D_MODEL / 32), tb>>>(Wo, woh, wol, D_MODEL, D_MODEL);

    // 2) projections (tensor cores, mma.sync)
    gemm_mma_kernel<<<dim3(D_MODEL / 128, MROWS / 128), 256, GSMEM>>>(
        xh, xl, wqh, wql, bq, qp, MROWS, D_MODEL, D_MODEL);
    gemm_mma_kernel<<<dim3(KV_DIM / 128, MROWS / 128), 256, GSMEM>>>(
        xh, xl, wkh, wkl, bk, kp, MROWS, KV_DIM, D_MODEL);
    gemm_mma_kernel<<<dim3(KV_DIM / 128, MROWS / 128), 256, GSMEM>>>(
        xh, xl, wvh, wvl, bv, vp, MROWS, KV_DIM, D_MODEL);

    // 3) attention (emits bf16 hi/lo o)
    flash_kernel<<<dim3(SEQ / 64, N_HEADS, BATCH), 256, flash_smem>>>();

    // 4) output projection into d_out
    gemm_mma_kernel<<<dim3(D_MODEL / 128, MROWS / 128), 256, GSMEM>>>(
        oh, ol, woh, wol, bo, out, MROWS, D_MODEL, D_MODEL);
}

// round 7
// speedup vs baseline: 2.7120x; 1.7110x over previous
#include <cuda_runtime.h>
#include <cuda_bf16.h>
#include <cuda_fp16.h>
#include <cstdint>

// ---------------------------------------------------------------------------
// GQA fp32. All GEMMs + flash attention on mma.sync tensor cores (split
// precision: bf16 hi/lo for projections, fp16 hi/lo for attention operands).
// R7: fix missing quad-reduction of softmax row sums (NaN root cause in R6).
// ---------------------------------------------------------------------------

#define D_MODEL 2048
#define KV_DIM  512
#define N_HEADS 32
#define DK      64
#define BATCH   4
#define SEQ     2048
#define MROWS   (BATCH * SEQ)   // 8192

// ---- device scratch (allocation-free) ----
__device__ __nv_bfloat16 g_xh[MROWS * D_MODEL];
__device__ __nv_bfloat16 g_xl[MROWS * D_MODEL];
__device__ __half g_qh[MROWS * D_MODEL];
__device__ __half g_ql[MROWS * D_MODEL];
__device__ __half g_kh[MROWS * KV_DIM];
__device__ __half g_kl[MROWS * KV_DIM];
__device__ __half g_vh[MROWS * KV_DIM];
__device__ __half g_vl[MROWS * KV_DIM];
__device__ __nv_bfloat16 g_oh[MROWS * D_MODEL];
__device__ __nv_bfloat16 g_ol[MROWS * D_MODEL];
__device__ __nv_bfloat16 g_wqt_h[D_MODEL * D_MODEL];
__device__ __nv_bfloat16 g_wqt_l[D_MODEL * D_MODEL];
__device__ __nv_bfloat16 g_wkt_h[KV_DIM * D_MODEL];
__device__ __nv_bfloat16 g_wkt_l[KV_DIM * D_MODEL];
__device__ __nv_bfloat16 g_wvt_h[KV_DIM * D_MODEL];
__device__ __nv_bfloat16 g_wvt_l[KV_DIM * D_MODEL];
__device__ __nv_bfloat16 g_wot_h[D_MODEL * D_MODEL];
__device__ __nv_bfloat16 g_wot_l[D_MODEL * D_MODEL];

// ==================== helpers ====================
__device__ __forceinline__ uint32_t smem_u32(const void* p) {
    uint32_t a;
    asm("{ .reg .u64 t; cvta.to.shared.u64 t, %1; cvt.u32.u64 %0, t; }" : "=r"(a) : "l"(p));
    return a;
}
__device__ __forceinline__ void cp16(uint32_t dst, const void* src) {
    asm volatile("cp.async.cg.shared.global [%0], [%1], 16;" :: "r"(dst), "l"(src));
}
#define CP_COMMIT() asm volatile("cp.async.commit_group;" ::: "memory")
#define CP_WAIT(n)  asm volatile("cp.async.wait_group %0;" :: "n"(n) : "memory")

__device__ __forceinline__ void ldm_x4(uint32_t* r, uint32_t addr) {
    asm volatile("ldmatrix.sync.aligned.m8n8.x4.shared.b16 {%0,%1,%2,%3}, [%4];"
        : "=r"(r[0]), "=r"(r[1]), "=r"(r[2]), "=r"(r[3]) : "r"(addr) : "memory");
}
__device__ __forceinline__ void ldm_x4_t(uint32_t* r, uint32_t addr) {
    asm volatile("ldmatrix.sync.aligned.m8n8.x4.trans.shared.b16 {%0,%1,%2,%3}, [%4];"
        : "=r"(r[0]), "=r"(r[1]), "=r"(r[2]), "=r"(r[3]) : "r"(addr) : "memory");
}
__device__ __forceinline__ void ldm_x2(uint32_t* r, uint32_t addr) {
    asm volatile("ldmatrix.sync.aligned.m8n8.x2.shared.b16 {%0,%1}, [%2];"
        : "=r"(r[0]), "=r"(r[1]) : "r"(addr) : "memory");
}
__device__ __forceinline__ void mma_bf(float* d, const uint32_t* a, const uint32_t* b) {
    asm volatile("mma.sync.aligned.m16n8k16.row.col.f32.bf16.bf16.f32 "
        "{%0,%1,%2,%3}, {%4,%5,%6,%7}, {%8,%9}, {%0,%1,%2,%3};"
        : "+f"(d[0]), "+f"(d[1]), "+f"(d[2]), "+f"(d[3])
        : "r"(a[0]), "r"(a[1]), "r"(a[2]), "r"(a[3]), "r"(b[0]), "r"(b[1]));
}
__device__ __forceinline__ void mma_h(float* d, const uint32_t* a, uint32_t b0, uint32_t b1) {
    asm volatile("mma.sync.aligned.m16n8k16.row.col.f32.f16.f16.f32 "
        "{%0,%1,%2,%3}, {%4,%5,%6,%7}, {%8,%9}, {%0,%1,%2,%3};"
        : "+f"(d[0]), "+f"(d[1]), "+f"(d[2]), "+f"(d[3])
        : "r"(a[0]), "r"(a[1]), "r"(a[2]), "r"(a[3]), "r"(b0), "r"(b1));
}
__device__ __forceinline__ uint32_t bfpack(__nv_bfloat16 a, __nv_bfloat16 b) {
    return (uint32_t)__bfloat16_as_ushort(a) | ((uint32_t)__bfloat16_as_ushort(b) << 16);
}
__device__ __forceinline__ uint32_t f16pack(float lo, float hi) {
    uint32_t r;
    asm("cvt.rn.f16x2.f32 %0, %1, %2;" : "=r"(r) : "f"(hi), "f"(lo));
    return r;
}
__device__ __forceinline__ float ex2f(float x) {
    float y;
    asm("ex2.approx.f32 %0, %1;" : "=f"(y) : "f"(x));
    return y;
}

// ==================== x split: fp32 -> bf16 hi + lo ====================
__global__ void __launch_bounds__(256)
split_kernel(const float* __restrict__ X, __nv_bfloat16* __restrict__ H,
             __nv_bfloat16* __restrict__ L, int n4)
{
    int i = blockIdx.x * 256 + threadIdx.x;
    if (i >= n4) return;
    float4 v = ((const float4*)X)[i];
    __nv_bfloat16 h0 = __float2bfloat16(v.x), h1 = __float2bfloat16(v.y);
    __nv_bfloat16 h2 = __float2bfloat16(v.z), h3 = __float2bfloat16(v.w);
    __nv_bfloat16 l0 = __float2bfloat16(v.x - __bfloat162float(h0));
    __nv_bfloat16 l1 = __float2bfloat16(v.y - __bfloat162float(h1));
    __nv_bfloat16 l2 = __float2bfloat16(v.z - __bfloat162float(h2));
    __nv_bfloat16 l3 = __float2bfloat16(v.w - __bfloat162float(h3));
    ((uint2*)H)[i] = make_uint2(bfpack(h0, h1), bfpack(h2, h3));
    ((uint2*)L)[i] = make_uint2(bfpack(l0, l1), bfpack(l2, l3));
}

// ==================== weight transpose + split ====================
__global__ void __launch_bounds__(256)
transpose_split_kernel(const float* __restrict__ W, __nv_bfloat16* __restrict__ Th,
                       __nv_bfloat16* __restrict__ Tl, int Kd, int Nd)
{
    __shared__ float tile[32][33];
    const int tx = threadIdx.x, ty = threadIdx.y;
    const int n0 = blockIdx.x * 32, k0 = blockIdx.y * 32;
#pragma unroll
    for (int j = ty; j < 32; j += 8)
        tile[j][tx] = W[(size_t)(k0 + j) * Nd + n0 + tx];
    __syncthreads();
#pragma unroll
    for (int j = ty; j < 32; j += 8) {
        float v = tile[tx][j];
        __nv_bfloat16 h = __float2bfloat16(v);
        __nv_bfloat16 lo = __float2bfloat16(v - __bfloat162float(h));
        Th[(size_t)(n0 + j) * Kd + k0 + tx] = h;
        Tl[(size_t)(n0 + j) * Kd + k0 + tx] = lo;
    }
}

// ==================== mma.sync bf16-split GEMM ====================
#define ROWB 80
#define TILEB (128 * ROWB)
#define STAGEB (4 * TILEB)
#define GSMEM (2 * STAGEB)

template <int OUT>
__global__ void __launch_bounds__(256, 1)
gemm_mma_kernel(const __nv_bfloat16* __restrict__ Ah, const __nv_bfloat16* __restrict__ Al,
                const __nv_bfloat16* __restrict__ Bh, const __nv_bfloat16* __restrict__ Bl,
                const float* __restrict__ bias, float* __restrict__ C,
                __half* __restrict__ Ch, __half* __restrict__ Cl,
                int M, int N, int K)
{
    extern __shared__ __align__(16) char smem[];
    const uint32_t sb = smem_u32(smem);
    const int tid = threadIdx.x;
    const int lane = tid & 31, w = tid >> 5;
    const int wr = w >> 2, wc = w & 3;
    const int row0 = blockIdx.y * 128, col0 = blockIdx.x * 128;
    const int nc = K >> 5;

    const __nv_bfloat16* srcs[4] = {
        Ah + (size_t)row0 * K, Al + (size_t)row0 * K,
        Bh + (size_t)col0 * K, Bl + (size_t)col0 * K };

    auto load_stage = [&](int kc, int st) {
        uint32_t stb = sb + st * STAGEB;
#pragma unroll
        for (int arr = 0; arr < 4; arr++) {
            const __nv_bfloat16* s = srcs[arr];
            uint32_t base = stb + arr * TILEB;
#pragma unroll
            for (int i = 0; i < 2; i++) {
                int chunk = tid + i * 256;
                int r = chunk >> 2, kq = chunk & 3;
                cp16(base + r * ROWB + kq * 16,
                     s + (size_t)r * K + kc * 32 + kq * 8);
            }
        }
    };

    float d[4][4][4];
#pragma unroll
    for (int mf = 0; mf < 4; mf++)
#pragma unroll
        for (int nf = 0; nf < 4; nf++)
#pragma unroll
            for (int e = 0; e < 4; e++) d[mf][nf][e] = 0.0f;

    load_stage(0, 0);
    CP_COMMIT();

    const uint32_t a_lane_off = (lane & 15) * ROWB + (lane >> 4) * 16;
    const uint32_t b_lane_off = (lane & 7) * ROWB + ((lane >> 3) & 1) * 16;

    for (int kc = 0; kc < nc; kc++) {
        const int st = kc & 1;
        if (kc + 1 < nc) { load_stage(kc + 1, st ^ 1); CP_COMMIT(); CP_WAIT(1); }
        else            { CP_WAIT(0); }
        __syncthreads();

        const uint32_t aH = sb + st * STAGEB + 0 * TILEB + wr * 64 * ROWB + a_lane_off;
        const uint32_t aL = sb + st * STAGEB + 1 * TILEB + wr * 64 * ROWB + a_lane_off;
        const uint32_t bH = sb + st * STAGEB + 2 * TILEB + wc * 32 * ROWB + b_lane_off;
        const uint32_t bL = sb + st * STAGEB + 3 * TILEB + wc * 32 * ROWB + b_lane_off;

#pragma unroll
        for (int ks = 0; ks < 2; ks++) {
            const uint32_t ko = ks * 32;
            uint32_t ah[4][4], al[4][4], bh[4][2], bl[4][2];
#pragma unroll
            for (int mf = 0; mf < 4; mf++) {
                ldm_x4(ah[mf], aH + mf * 16 * ROWB + ko);
                ldm_x4(al[mf], aL + mf * 16 * ROWB + ko);
            }
#pragma unroll
            for (int nf = 0; nf < 4; nf++) {
                ldm_x2(bh[nf], bH + nf * 8 * ROWB + ko);
                ldm_x2(bl[nf], bL + nf * 8 * ROWB + ko);
            }
#pragma unroll
            for (int mf = 0; mf < 4; mf++)
#pragma unroll
                for (int nf = 0; nf < 4; nf++) {
                    mma_bf(d[mf][nf], ah[mf], bh[nf]);
                    mma_bf(d[mf][nf], ah[mf], bl[nf]);
                    mma_bf(d[mf][nf], al[mf], bh[nf]);
                }
        }
        __syncthreads();
    }

#pragma unroll
    for (int mf = 0; mf < 4; mf++) {
        const int r = row0 + wr * 64 + mf * 16 + (lane >> 2);
#pragma unroll
        for (int nf = 0; nf < 4; nf++) {
            const int c = col0 + wc * 32 + nf * 8 + (lane & 3) * 2;
            const float b0 = bias[c], b1 = bias[c + 1];
            float v00 = d[mf][nf][0] + b0, v01 = d[mf][nf][1] + b1;
            float v10 = d[mf][nf][2] + b0, v11 = d[mf][nf][3] + b1;
            if (OUT == 0) {
                *(float2*)(C + (size_t)r * N + c) = make_float2(v00, v01);
                *(float2*)(C + (size_t)(r + 8) * N + c) = make_float2(v10, v11);
            } else {
                __half h00 = __float2half_rn(v00), h01 = __float2half_rn(v01);
                __half h10 = __float2half_rn(v10), h11 = __float2half_rn(v11);
                __half e00 = __float2half_rn(v00 - __half2float(h00));
                __half e01 = __float2half_rn(v01 - __half2float(h01));
                __half e10 = __float2half_rn(v10 - __half2float(h10));
                __half e11 = __float2half_rn(v11 - __half2float(h11));
                *(__half2*)(Ch + (size_t)r * N + c)       = __halves2half2(h00, h01);
                *(__half2*)(Ch + (size_t)(r + 8) * N + c) = __halves2half2(h10, h11);
                *(__half2*)(Cl + (size_t)r * N + c)       = __halves2half2(e00, e01);
                *(__half2*)(Cl + (size_t)(r + 8) * N + c) = __halves2half2(e10, e11);
            }
        }
    }
}

// ==================== flash attention on mma.sync (fp16 split) ====================
#define ROWF 144
#define QH_OFF 0
#define QL_OFF (64 * ROWF)
#define STG_OFF (2 * 64 * ROWF)
#define KH_P 0
#define KL_P (64 * ROWF)
#define VH_P (2 * 64 * ROWF)
#define VL_P (3 * 64 * ROWF)
#define STG_SZ (4 * 64 * ROWF)
#define FSMEM (STG_OFF + 2 * STG_SZ)   // 92160

__global__ void __launch_bounds__(128, 2)
flash_mma_kernel()
{
    extern __shared__ __align__(16) char fsm[];
    const uint32_t sb = smem_u32(fsm);
    const int tid = threadIdx.x;
    const int lane = tid & 31, w = tid >> 5;
    const int b = blockIdx.z, h = blockIdx.y;
    const int qi = (int)gridDim.x - 1 - (int)blockIdx.x;
    const int q0 = qi * 64;
    const int kvh = h >> 2;
    const size_t bS = (size_t)b * SEQ;

    const __half* qhp = g_qh + (bS + q0) * D_MODEL + h * DK;
    const __half* qlp = g_ql + (bS + q0) * D_MODEL + h * DK;
    const __half* khp = g_kh + bS * KV_DIM + kvh * DK;
    const __half* klp = g_kl + bS * KV_DIM + kvh * DK;
    const __half* vhp = g_vh + bS * KV_DIM + kvh * DK;
    const __half* vlp = g_vl + bS * KV_DIM + kvh * DK;

    auto load_kv = [&](int t, int st) {
        uint32_t base = sb + STG_OFF + st * STG_SZ;
        const size_t g0 = (size_t)(t * 64);
#pragma unroll
        for (int i = 0; i < 4; i++) {
            int ch = tid + i * 128;
            int r = ch >> 3, off = ch & 7;
            size_t g = (g0 + r) * KV_DIM + off * 8;
            uint32_t so = r * ROWF + off * 16;
            cp16(base + KH_P + so, khp + g);
            cp16(base + KL_P + so, klp + g);
            cp16(base + VH_P + so, vhp + g);
            cp16(base + VL_P + so, vlp + g);
        }
    };

#pragma unroll
    for (int i = 0; i < 4; i++) {
        int ch = tid + i * 128;
        int r = ch >> 3, off = ch & 7;
        uint32_t so = r * ROWF + off * 16;
        cp16(sb + QH_OFF + so, qhp + (size_t)r * D_MODEL + off * 8);
        cp16(sb + QL_OFF + so, qlp + (size_t)r * D_MODEL + off * 8);
    }
    CP_COMMIT();
    load_kv(0, 0);
    CP_COMMIT();
    CP_WAIT(0);
    __syncthreads();

    uint32_t qh[4][4], ql[4][4];
    {
        const uint32_t aoff = (uint32_t)((w * 16 + (lane & 15)) * ROWF + (lane >> 4) * 16);
#pragma unroll
        for (int kf = 0; kf < 4; kf++) {
            ldm_x4(qh[kf], sb + QH_OFF + aoff + kf * 32);
            ldm_x4(ql[kf], sb + QL_OFF + aoff + kf * 32);
        }
    }

    float o[8][4];
#pragma unroll
    for (int nf = 0; nf < 8; nf++)
#pragma unroll
        for (int e = 0; e < 4; e++) o[nf][e] = 0.0f;
    float m0 = -1e30f, m1 = -1e30f, l0 = 0.0f, l1 = 0.0f;
    const float Cs = 0.18033688011112042f;   // (1/8) * log2(e)

    const uint32_t krow = ((((lane >> 3) & 1) * 8 + (lane & 7))) * ROWF;
    const uint32_t kcol = ((lane >> 4) & 1) * 16;
    const uint32_t vrow = (((lane >> 4) & 1) * 8 + (lane & 7));
    const uint32_t vcol = (((lane >> 3) & 1) * 8);

    for (int t = 0; t <= qi; t++) {
        const int st = t & 1;
        if (t < qi) { load_kv(t + 1, st ^ 1); CP_COMMIT(); CP_WAIT(1); }
        else        { CP_WAIT(0); }
        __syncthreads();
        const uint32_t kb = sb + STG_OFF + st * STG_SZ;

        // ---- S = Q K^T (3-MMA fp16 split) ----
        float s[8][4];
#pragma unroll
        for (int nf = 0; nf < 8; nf++)
#pragma unroll
            for (int e = 0; e < 4; e++) s[nf][e] = 0.0f;

#pragma unroll
        for (int kf = 0; kf < 4; kf++) {
#pragma unroll
            for (int np = 0; np < 4; np++) {
                const uint32_t addr = kb + np * (16 * ROWF) + krow + kf * 32 + kcol;
                uint32_t kh4[4], kl4[4];
                ldm_x4(kh4, addr + KH_P);
                ldm_x4(kl4, addr + KL_P);
                mma_h(s[2 * np],     qh[kf], kh4[0], kh4[2]);
                mma_h(s[2 * np],     ql[kf], kh4[0], kh4[2]);
                mma_h(s[2 * np],     qh[kf], kl4[0], kl4[2]);
                mma_h(s[2 * np + 1], qh[kf], kh4[1], kh4[3]);
                mma_h(s[2 * np + 1], ql[kf], kh4[1], kh4[3]);
                mma_h(s[2 * np + 1], qh[kf], kl4[1], kl4[3]);
            }
        }

        if (t == qi) {
            const int r0 = w * 16 + (lane >> 2);
            const int cb = 2 * (lane & 3);
#pragma unroll
            for (int nf = 0; nf < 8; nf++) {
                int c0 = nf * 8 + cb;
                if (c0     > r0)     s[nf][0] = -1e30f;
                if (c0 + 1 > r0)     s[nf][1] = -1e30f;
                if (c0     > r0 + 8) s[nf][2] = -1e30f;
                if (c0 + 1 > r0 + 8) s[nf][3] = -1e30f;
            }
        }

        // ---- online softmax (rows lane>>2 and lane>>2+8) ----
        float mx0 = s[0][0], mx1 = s[0][2];
#pragma unroll
        for (int nf = 0; nf < 8; nf++) {
            mx0 = fmaxf(mx0, fmaxf(s[nf][0], s[nf][1]));
            mx1 = fmaxf(mx1, fmaxf(s[nf][2], s[nf][3]));
        }
        mx0 = fmaxf(mx0, __shfl_xor_sync(0xffffffffu, mx0, 1));
        mx0 = fmaxf(mx0, __shfl_xor_sync(0xffffffffu, mx0, 2));
        mx1 = fmaxf(mx1, __shfl_xor_sync(0xffffffffu, mx1, 1));
        mx1 = fmaxf(mx1, __shfl_xor_sync(0xffffffffu, mx1, 2));
        const float mn0 = fmaxf(m0, mx0), mn1 = fmaxf(m1, mx1);
        const float a0 = ex2f((m0 - mn0) * Cs);
        const float a1 = ex2f((m1 - mn1) * Cs);
        m0 = mn0; m1 = mn1;
        const float mc0 = mn0 * Cs, mc1 = mn1 * Cs;

        float rs0 = 0.0f, rs1 = 0.0f;
#pragma unroll
        for (int nf = 0; nf < 8; nf++) {
            s[nf][0] = ex2f(fmaf(s[nf][0], Cs, -mc0));
            s[nf][1] = ex2f(fmaf(s[nf][1], Cs, -mc0));
            s[nf][2] = ex2f(fmaf(s[nf][2], Cs, -mc1));
            s[nf][3] = ex2f(fmaf(s[nf][3], Cs, -mc1));
            rs0 += s[nf][0] + s[nf][1];
            rs1 += s[nf][2] + s[nf][3];
        }
        // R7 FIX: reduce row sums across the 4-lane quad (was missing -> l=0
        // for fully-masked lanes -> 1/0 * 0 = NaN, and wrong l everywhere).
        rs0 += __shfl_xor_sync(0xffffffffu, rs0, 1);
        rs0 += __shfl_xor_sync(0xffffffffu, rs0, 2);
        rs1 += __shfl_xor_sync(0xffffffffu, rs1, 1);
        rs1 += __shfl_xor_sync(0xffffffffu, rs1, 2);
        l0 = l0 * a0 + rs0;
        l1 = l1 * a1 + rs1;
#pragma unroll
        for (int nf = 0; nf < 8; nf++) {
            o[nf][0] *= a0; o[nf][1] *= a0;
            o[nf][2] *= a1; o[nf][3] *= a1;
        }

        // ---- P fragments (fp16, in-register) ----
        uint32_t pa[4][4];
#pragma unroll
        for (int kf = 0; kf < 4; kf++) {
            pa[kf][0] = f16pack(s[2 * kf][0],     s[2 * kf][1]);
            pa[kf][1] = f16pack(s[2 * kf][2],     s[2 * kf][3]);
            pa[kf][2] = f16pack(s[2 * kf + 1][0], s[2 * kf + 1][1]);
            pa[kf][3] = f16pack(s[2 * kf + 1][2], s[2 * kf + 1][3]);
        }

        // ---- O += P V (V fp16 hi/lo, 2 MMAs) ----
#pragma unroll
        for (int kf = 0; kf < 4; kf++) {
#pragma unroll
            for (int np = 0; np < 4; np++) {
                const uint32_t addr = kb + VH_P + (kf * 16 + vrow) * ROWF + (np * 16 + vcol) * 2;
                uint32_t vh4[4], vl4[4];
                ldm_x4_t(vh4, addr);
                ldm_x4_t(vl4, addr + (VL_P - VH_P));
                mma_h(o[2 * np],     pa[kf], vh4[0], vh4[2]);
                mma_h(o[2 * np],     pa[kf], vl4[0], vl4[2]);
                mma_h(o[2 * np + 1], pa[kf], vh4[1], vh4[3]);
                mma_h(o[2 * np + 1], pa[kf], vl4[1], vl4[3]);
            }
        }
        __syncthreads();
    }

    // ---- epilogue: normalize, write bf16 hi/lo o ----
    const float inv0 = __fdividef(1.0f, l0);
    const float inv1 = __fdividef(1.0f, l1);
    const size_t gr0 = (bS + q0 + w * 16 + (lane >> 2)) * D_MODEL + h * DK;
    const size_t gr1 = gr0 + 8 * D_MODEL;
#pragma unroll
    for (int nf = 0; nf < 8; nf++) {
        const int c = nf * 8 + 2 * (lane & 3);
        float v0 = o[nf][0] * inv0, v1 = o[nf][1] * inv0;
        float v2 = o[nf][2] * inv1, v3 = o[nf][3] * inv1;
        __nv_bfloat16 h0 = __float2bfloat16(v0), h1 = __float2bfloat16(v1);
        __nv_bfloat16 h2 = __float2bfloat16(v2), h3 = __float2bfloat16(v3);
        __nv_bfloat16 e0 = __float2bfloat16(v0 - __bfloat162float(h0));
        __nv_bfloat16 e1 = __float2bfloat16(v1 - __bfloat162float(h1));
        __nv_bfloat16 e2 = __float2bfloat16(v2 - __bfloat162float(h2));
        __nv_bfloat16 e3 = __float2bfloat16(v3 - __bfloat162float(h3));
        *(uint32_t*)(g_oh + gr0 + c) = bfpack(h0, h1);
        *(uint32_t*)(g_ol + gr0 + c) = bfpack(e0, e1);
        *(uint32_t*)(g_oh + gr1 + c) = bfpack(h2, h3);
        *(uint32_t*)(g_ol + gr1 + c) = bfpack(e2, e3);
    }
}

// ==================== launch ====================
extern "C" void kernel_launch(void* const* d_in, const int* in_sizes, int n_in,
                              void* d_out, int out_size)
{
    const float* x  = (const float*)d_in[0];
    const float* Wq = (const float*)d_in[1];
    const float* bq = (const float*)d_in[2];
    const float* Wk = (const float*)d_in[3];
    const float* bk = (const float*)d_in[4];
    const float* Wv = (const float*)d_in[5];
    const float* bv = (const float*)d_in[6];
    const float* Wo = (const float*)d_in[7];
    const float* bo = (const float*)d_in[8];
    float* out = (float*)d_out;

    __nv_bfloat16 *xh, *xl, *oh, *ol;
    cudaGetSymbolAddress((void**)&xh, g_xh);
    cudaGetSymbolAddress((void**)&xl, g_xl);
    cudaGetSymbolAddress((void**)&oh, g_oh);
    cudaGetSymbolAddress((void**)&ol, g_ol);
    __half *qh, *ql, *kh, *kl, *vh, *vl;
    cudaGetSymbolAddress((void**)&qh, g_qh);
    cudaGetSymbolAddress((void**)&ql, g_ql);
    cudaGetSymbolAddress((void**)&kh, g_kh);
    cudaGetSymbolAddress((void**)&kl, g_kl);
    cudaGetSymbolAddress((void**)&vh, g_vh);
    cudaGetSymbolAddress((void**)&vl, g_vl);
    __nv_bfloat16 *wqh, *wql, *wkh, *wkl, *wvh, *wvl, *woh, *wol;
    cudaGetSymbolAddress((void**)&wqh, g_wqt_h);
    cudaGetSymbolAddress((void**)&wql, g_wqt_l);
    cudaGetSymbolAddress((void**)&wkh, g_wkt_h);
    cudaGetSymbolAddress((void**)&wkl, g_wkt_l);
    cudaGetSymbolAddress((void**)&wvh, g_wvt_h);
    cudaGetSymbolAddress((void**)&wvl, g_wvt_l);
    cudaGetSymbolAddress((void**)&woh, g_wot_h);
    cudaGetSymbolAddress((void**)&wol, g_wot_l);

    cudaFuncSetAttribute((const void*)gemm_mma_kernel<0>,
                         cudaFuncAttributeMaxDynamicSharedMemorySize, GSMEM);
    cudaFuncSetAttribute((const void*)gemm_mma_kernel<1>,
                         cudaFuncAttributeMaxDynamicSharedMemorySize, GSMEM);
    cudaFuncSetAttribute((const void*)flash_mma_kernel,
                         cudaFuncAttributeMaxDynamicSharedMemorySize, FSMEM);

    const int n4 = MROWS * D_MODEL / 4;
    split_kernel<<<(n4 + 255) / 256, 256>>>(x, xh, xl, n4);
    dim3 tb(32, 8);
    transpose_split_kernel<<<dim3(D_MODEL / 32, D_MODEL / 32), tb>>>(Wq, wqh, wql, D_MODEL, D_MODEL);
    transpose_split_kernel<<<dim3(KV_DIM  / 32, D_MODEL / 32), tb>>>(Wk, wkh, wkl, D_MODEL, KV_DIM);
    transpose_split_kernel<<<dim3(KV_DIM  / 32, D_MODEL / 32), tb>>>(Wv, wvh, wvl, D_MODEL, KV_DIM);
    transpose_split_kernel<<<dim3(D_MODEL / 32, D_MODEL / 32), tb>>>(Wo, woh, wol, D_MODEL, D_MODEL);

    gemm_mma_kernel<1><<<dim3(D_MODEL / 128, MROWS / 128), 256, GSMEM>>>(
        xh, xl, wqh, wql, bq, nullptr, qh, ql, MROWS, D_MODEL, D_MODEL);
    gemm_mma_kernel<1><<<dim3(KV_DIM / 128, MROWS / 128), 256, GSMEM>>>(
        xh, xl, wkh, wkl, bk, nullptr, kh, kl, MROWS, KV_DIM, D_MODEL);
    gemm_mma_kernel<1><<<dim3(KV_DIM / 128, MROWS / 128), 256, GSMEM>>>(
        xh, xl, wvh, wvl, bv, nullptr, vh, vl, MROWS, KV_DIM, D_MODEL);

    flash_mma_kernel<<<dim3(SEQ / 64, N_HEADS, BATCH), 128, FSMEM>>>();

    gemm_mma_kernel<0><<<dim3(D_MODEL / 128, MROWS / 128), 256, GSMEM>>>(
        oh, ol, woh, wol, bo, out, nullptr, nullptr, MROWS, D_MODEL, D_MODEL);
}

// round 8
// speedup vs baseline: 3.8996x; 1.4379x over previous
#include <cuda_runtime.h>
#include <cuda_fp16.h>
#include <cstdint>

// ---------------------------------------------------------------------------
// GQA fp32 on mma.sync fp16 tensor cores. 2-MMA split GEMMs (A = fp16 hi/lo,
// W = single fp16), flash attention with Q split / K,V single fp16.
// ---------------------------------------------------------------------------

#define D_MODEL 2048
#define KV_DIM  512
#define N_HEADS 32
#define DK      64
#define BATCH   4
#define SEQ     2048
#define MROWS   (BATCH * SEQ)   // 8192

// ---- device scratch (allocation-free) ----
__device__ __half g_xh[MROWS * D_MODEL];
__device__ __half g_xl[MROWS * D_MODEL];
__device__ __half g_qh[MROWS * D_MODEL];
__device__ __half g_ql[MROWS * D_MODEL];
__device__ __half g_k [MROWS * KV_DIM];
__device__ __half g_v [MROWS * KV_DIM];
__device__ __half g_oh[MROWS * D_MODEL];
__device__ __half g_ol[MROWS * D_MODEL];
__device__ __half g_wqt[D_MODEL * D_MODEL];
__device__ __half g_wkt[KV_DIM * D_MODEL];
__device__ __half g_wvt[KV_DIM * D_MODEL];
__device__ __half g_wot[D_MODEL * D_MODEL];

// ==================== helpers ====================
__device__ __forceinline__ uint32_t smem_u32(const void* p) {
    uint32_t a;
    asm("{ .reg .u64 t; cvta.to.shared.u64 t, %1; cvt.u32.u64 %0, t; }" : "=r"(a) : "l"(p));
    return a;
}
__device__ __forceinline__ void cp16(uint32_t dst, const void* src) {
    asm volatile("cp.async.cg.shared.global [%0], [%1], 16;" :: "r"(dst), "l"(src));
}
#define CP_COMMIT() asm volatile("cp.async.commit_group;" ::: "memory")
#define CP_WAIT(n)  asm volatile("cp.async.wait_group %0;" :: "n"(n) : "memory")

__device__ __forceinline__ void ldm_x4(uint32_t* r, uint32_t addr) {
    asm volatile("ldmatrix.sync.aligned.m8n8.x4.shared.b16 {%0,%1,%2,%3}, [%4];"
        : "=r"(r[0]), "=r"(r[1]), "=r"(r[2]), "=r"(r[3]) : "r"(addr) : "memory");
}
__device__ __forceinline__ void ldm_x4_t(uint32_t* r, uint32_t addr) {
    asm volatile("ldmatrix.sync.aligned.m8n8.x4.trans.shared.b16 {%0,%1,%2,%3}, [%4];"
        : "=r"(r[0]), "=r"(r[1]), "=r"(r[2]), "=r"(r[3]) : "r"(addr) : "memory");
}
__device__ __forceinline__ void ldm_x2(uint32_t* r, uint32_t addr) {
    asm volatile("ldmatrix.sync.aligned.m8n8.x2.shared.b16 {%0,%1}, [%2];"
        : "=r"(r[0]), "=r"(r[1]) : "r"(addr) : "memory");
}
__device__ __forceinline__ void mma_h(float* d, const uint32_t* a, uint32_t b0, uint32_t b1) {
    asm volatile("mma.sync.aligned.m16n8k16.row.col.f32.f16.f16.f32 "
        "{%0,%1,%2,%3}, {%4,%5,%6,%7}, {%8,%9}, {%0,%1,%2,%3};"
        : "+f"(d[0]), "+f"(d[1]), "+f"(d[2]), "+f"(d[3])
        : "r"(a[0]), "r"(a[1]), "r"(a[2]), "r"(a[3]), "r"(b0), "r"(b1));
}
__device__ __forceinline__ uint32_t f16pack(float lo, float hi) {
    uint32_t r;
    asm("cvt.rn.f16x2.f32 %0, %1, %2;" : "=r"(r) : "f"(hi), "f"(lo));
    return r;
}
__device__ __forceinline__ float ex2f(float x) {
    float y;
    asm("ex2.approx.f32 %0, %1;" : "=f"(y) : "f"(x));
    return y;
}
__device__ __forceinline__ uint32_t hpack(__half a, __half b) {
    return (uint32_t)__half_as_ushort(a) | ((uint32_t)__half_as_ushort(b) << 16);
}

// ==================== x split: fp32 -> fp16 hi + lo ====================
__global__ void __launch_bounds__(256)
split_kernel(const float* __restrict__ X, __half* __restrict__ H,
             __half* __restrict__ L, int n4)
{
    int i = blockIdx.x * 256 + threadIdx.x;
    if (i >= n4) return;
    float4 v = ((const float4*)X)[i];
    __half h0 = __float2half_rn(v.x), h1 = __float2half_rn(v.y);
    __half h2 = __float2half_rn(v.z), h3 = __float2half_rn(v.w);
    __half l0 = __float2half_rn(v.x - __half2float(h0));
    __half l1 = __float2half_rn(v.y - __half2float(h1));
    __half l2 = __float2half_rn(v.z - __half2float(h2));
    __half l3 = __float2half_rn(v.w - __half2float(h3));
    ((uint2*)H)[i] = make_uint2(hpack(h0, h1), hpack(h2, h3));
    ((uint2*)L)[i] = make_uint2(hpack(l0, l1), hpack(l2, l3));
}

// ==================== weight transpose -> fp16 [N][K] ====================
__global__ void __launch_bounds__(256)
transpose_h_kernel(const float* __restrict__ W, __half* __restrict__ T, int Kd, int Nd)
{
    __shared__ float tile[32][33];
    const int tx = threadIdx.x, ty = threadIdx.y;
    const int n0 = blockIdx.x * 32, k0 = blockIdx.y * 32;
#pragma unroll
    for (int j = ty; j < 32; j += 8)
        tile[j][tx] = W[(size_t)(k0 + j) * Nd + n0 + tx];
    __syncthreads();
#pragma unroll
    for (int j = ty; j < 32; j += 8)
        T[(size_t)(n0 + j) * Kd + k0 + tx] = __float2half_rn(tile[tx][j]);
}

// ==================== 2-MMA fp16-split GEMM ====================
// C = (Ah+Al)[M,K] @ B^T[N,K] + bias.
// OUT=0: fp32 C. OUT=1: fp16 hi/lo (Ch,Cl). OUT=2: fp16 single (Ch).
#define ROWB 80
#define TILEB (128 * ROWB)
#define STAGEB (3 * TILEB)            // Ah, Al, B
#define GSMEM (2 * STAGEB)            // 61440

template <int OUT>
__global__ void __launch_bounds__(256, 1)
gemm2_kernel(const __half* __restrict__ Ah, const __half* __restrict__ Al,
             const __half* __restrict__ B, const float* __restrict__ bias,
             float* __restrict__ C, __half* __restrict__ Ch, __half* __restrict__ Cl,
             int M, int N, int K)
{
    extern __shared__ __align__(16) char smem[];
    const uint32_t sb = smem_u32(smem);
    const int tid = threadIdx.x;
    const int lane = tid & 31, w = tid >> 5;
    const int wr = w >> 2, wc = w & 3;
    const int row0 = blockIdx.y * 128, col0 = blockIdx.x * 128;
    const int nc = K >> 5;

    const __half* srcs[3] = {
        Ah + (size_t)row0 * K, Al + (size_t)row0 * K, B + (size_t)col0 * K };

    auto load_stage = [&](int kc, int st) {
        uint32_t stb = sb + st * STAGEB;
#pragma unroll
        for (int arr = 0; arr < 3; arr++) {
            const __half* s = srcs[arr];
            uint32_t base = stb + arr * TILEB;
#pragma unroll
            for (int i = 0; i < 2; i++) {
                int chunk = tid + i * 256;
                int r = chunk >> 2, kq = chunk & 3;
                cp16(base + r * ROWB + kq * 16,
                     s + (size_t)r * K + kc * 32 + kq * 8);
            }
        }
    };

    float d[4][4][4];
#pragma unroll
    for (int mf = 0; mf < 4; mf++)
#pragma unroll
        for (int nf = 0; nf < 4; nf++)
#pragma unroll
            for (int e = 0; e < 4; e++) d[mf][nf][e] = 0.0f;

    load_stage(0, 0);
    CP_COMMIT();

    const uint32_t a_lane_off = (lane & 15) * ROWB + (lane >> 4) * 16;
    const uint32_t b_lane_off = (lane & 7) * ROWB + ((lane >> 3) & 1) * 16;

    for (int kc = 0; kc < nc; kc++) {
        const int st = kc & 1;
        if (kc + 1 < nc) { load_stage(kc + 1, st ^ 1); CP_COMMIT(); CP_WAIT(1); }
        else            { CP_WAIT(0); }
        __syncthreads();

        const uint32_t aH = sb + st * STAGEB + 0 * TILEB + wr * 64 * ROWB + a_lane_off;
        const uint32_t aL = sb + st * STAGEB + 1 * TILEB + wr * 64 * ROWB + a_lane_off;
        const uint32_t bB = sb + st * STAGEB + 2 * TILEB + wc * 32 * ROWB + b_lane_off;

#pragma unroll
        for (int ks = 0; ks < 2; ks++) {
            const uint32_t ko = ks * 32;
            uint32_t ah[4][4], al[4][4], bh[4][2];
#pragma unroll
            for (int mf = 0; mf < 4; mf++) {
                ldm_x4(ah[mf], aH + mf * 16 * ROWB + ko);
                ldm_x4(al[mf], aL + mf * 16 * ROWB + ko);
            }
#pragma unroll
            for (int nf = 0; nf < 4; nf++)
                ldm_x2(bh[nf], bB + nf * 8 * ROWB + ko);
#pragma unroll
            for (int mf = 0; mf < 4; mf++)
#pragma unroll
                for (int nf = 0; nf < 4; nf++) {
                    mma_h(d[mf][nf], ah[mf], bh[nf][0], bh[nf][1]);
                    mma_h(d[mf][nf], al[mf], bh[nf][0], bh[nf][1]);
                }
        }
        __syncthreads();
    }

#pragma unroll
    for (int mf = 0; mf < 4; mf++) {
        const int r = row0 + wr * 64 + mf * 16 + (lane >> 2);
#pragma unroll
        for (int nf = 0; nf < 4; nf++) {
            const int c = col0 + wc * 32 + nf * 8 + (lane & 3) * 2;
            const float b0 = bias[c], b1 = bias[c + 1];
            float v00 = d[mf][nf][0] + b0, v01 = d[mf][nf][1] + b1;
            float v10 = d[mf][nf][2] + b0, v11 = d[mf][nf][3] + b1;
            if (OUT == 0) {
                *(float2*)(C + (size_t)r * N + c) = make_float2(v00, v01);
                *(float2*)(C + (size_t)(r + 8) * N + c) = make_float2(v10, v11);
            } else {
                __half h00 = __float2half_rn(v00), h01 = __float2half_rn(v01);
                __half h10 = __float2half_rn(v10), h11 = __float2half_rn(v11);
                *(uint32_t*)(Ch + (size_t)r * N + c)       = hpack(h00, h01);
                *(uint32_t*)(Ch + (size_t)(r + 8) * N + c) = hpack(h10, h11);
                if (OUT == 1) {
                    __half e00 = __float2half_rn(v00 - __half2float(h00));
                    __half e01 = __float2half_rn(v01 - __half2float(h01));
                    __half e10 = __float2half_rn(v10 - __half2float(h10));
                    __half e11 = __float2half_rn(v11 - __half2float(h11));
                    *(uint32_t*)(Cl + (size_t)r * N + c)       = hpack(e00, e01);
                    *(uint32_t*)(Cl + (size_t)(r + 8) * N + c) = hpack(e10, e11);
                }
            }
        }
    }
}

// ==================== flash attention (Q split, K/V single fp16) ====================
// 128 threads / 4 warps; BR=BC=64, DK=64. S = Qh*K + Ql*K; PV = P*V.
#define ROWF 144
#define QH_OFF 0
#define QL_OFF (64 * ROWF)             // 9216
#define STG_OFF (2 * 64 * ROWF)        // 18432
#define K_P 0
#define V_P (64 * ROWF)
#define STG_SZ (2 * 64 * ROWF)         // 18432
#define FSMEM (STG_OFF + 2 * STG_SZ)   // 55296

__global__ void __launch_bounds__(128, 2)
flash_mma_kernel()
{
    extern __shared__ __align__(16) char fsm[];
    const uint32_t sb = smem_u32(fsm);
    const int tid = threadIdx.x;
    const int lane = tid & 31, w = tid >> 5;
    const int b = blockIdx.z, h = blockIdx.y;
    const int qi = (int)gridDim.x - 1 - (int)blockIdx.x;
    const int q0 = qi * 64;
    const int kvh = h >> 2;
    const size_t bS = (size_t)b * SEQ;

    const __half* qhp = g_qh + (bS + q0) * D_MODEL + h * DK;
    const __half* qlp = g_ql + (bS + q0) * D_MODEL + h * DK;
    const __half* kp  = g_k + bS * KV_DIM + kvh * DK;
    const __half* vp  = g_v + bS * KV_DIM + kvh * DK;

    auto load_kv = [&](int t, int st) {
        uint32_t base = sb + STG_OFF + st * STG_SZ;
        const size_t g0 = (size_t)(t * 64);
#pragma unroll
        for (int i = 0; i < 4; i++) {
            int ch = tid + i * 128;
            int r = ch >> 3, off = ch & 7;
            size_t g = (g0 + r) * KV_DIM + off * 8;
            uint32_t so = r * ROWF + off * 16;
            cp16(base + K_P + so, kp + g);
            cp16(base + V_P + so, vp + g);
        }
    };

#pragma unroll
    for (int i = 0; i < 4; i++) {
        int ch = tid + i * 128;
        int r = ch >> 3, off = ch & 7;
        uint32_t so = r * ROWF + off * 16;
        cp16(sb + QH_OFF + so, qhp + (size_t)r * D_MODEL + off * 8);
        cp16(sb + QL_OFF + so, qlp + (size_t)r * D_MODEL + off * 8);
    }
    CP_COMMIT();
    load_kv(0, 0);
    CP_COMMIT();
    CP_WAIT(0);
    __syncthreads();

    uint32_t qh[4][4], ql[4][4];
    {
        const uint32_t aoff = (uint32_t)((w * 16 + (lane & 15)) * ROWF + (lane >> 4) * 16);
#pragma unroll
        for (int kf = 0; kf < 4; kf++) {
            ldm_x4(qh[kf], sb + QH_OFF + aoff + kf * 32);
            ldm_x4(ql[kf], sb + QL_OFF + aoff + kf * 32);
        }
    }

    float o[8][4];
#pragma unroll
    for (int nf = 0; nf < 8; nf++)
#pragma unroll
        for (int e = 0; e < 4; e++) o[nf][e] = 0.0f;
    float m0 = -1e30f, m1 = -1e30f, l0 = 0.0f, l1 = 0.0f;
    const float Cs = 0.18033688011112042f;   // (1/8) * log2(e)

    const uint32_t krow = ((((lane >> 3) & 1) * 8 + (lane & 7))) * ROWF;
    const uint32_t kcol = ((lane >> 4) & 1) * 16;
    const uint32_t vrow = (((lane >> 4) & 1) * 8 + (lane & 7));
    const uint32_t vcol = (((lane >> 3) & 1) * 8);

    for (int t = 0; t <= qi; t++) {
        const int st = t & 1;
        if (t < qi) { load_kv(t + 1, st ^ 1); CP_COMMIT(); CP_WAIT(1); }
        else        { CP_WAIT(0); }
        __syncthreads();
        const uint32_t kb = sb + STG_OFF + st * STG_SZ;

        // ---- S = Q K^T (Q hi/lo, K single: 2 MMAs per fragment) ----
        float s[8][4];
#pragma unroll
        for (int nf = 0; nf < 8; nf++)
#pragma unroll
            for (int e = 0; e < 4; e++) s[nf][e] = 0.0f;

#pragma unroll
        for (int kf = 0; kf < 4; kf++) {
#pragma unroll
            for (int np = 0; np < 4; np++) {
                const uint32_t addr = kb + K_P + np * (16 * ROWF) + krow + kf * 32 + kcol;
                uint32_t k4[4];
                ldm_x4(k4, addr);
                mma_h(s[2 * np],     qh[kf], k4[0], k4[2]);
                mma_h(s[2 * np],     ql[kf], k4[0], k4[2]);
                mma_h(s[2 * np + 1], qh[kf], k4[1], k4[3]);
                mma_h(s[2 * np + 1], ql[kf], k4[1], k4[3]);
            }
        }

        if (t == qi) {
            const int r0 = w * 16 + (lane >> 2);
            const int cb = 2 * (lane & 3);
#pragma unroll
            for (int nf = 0; nf < 8; nf++) {
                int c0 = nf * 8 + cb;
                if (c0     > r0)     s[nf][0] = -1e30f;
                if (c0 + 1 > r0)     s[nf][1] = -1e30f;
                if (c0     > r0 + 8) s[nf][2] = -1e30f;
                if (c0 + 1 > r0 + 8) s[nf][3] = -1e30f;
            }
        }

        // ---- online softmax ----
        float mx0 = s[0][0], mx1 = s[0][2];
#pragma unroll
        for (int nf = 0; nf < 8; nf++) {
            mx0 = fmaxf(mx0, fmaxf(s[nf][0], s[nf][1]));
            mx1 = fmaxf(mx1, fmaxf(s[nf][2], s[nf][3]));
        }
        mx0 = fmaxf(mx0, __shfl_xor_sync(0xffffffffu, mx0, 1));
        mx0 = fmaxf(mx0, __shfl_xor_sync(0xffffffffu, mx0, 2));
        mx1 = fmaxf(mx1, __shfl_xor_sync(0xffffffffu, mx1, 1));
        mx1 = fmaxf(mx1, __shfl_xor_sync(0xffffffffu, mx1, 2));
        const float mn0 = fmaxf(m0, mx0), mn1 = fmaxf(m1, mx1);
        const float a0 = ex2f((m0 - mn0) * Cs);
        const float a1 = ex2f((m1 - mn1) * Cs);
        m0 = mn0; m1 = mn1;
        const float mc0 = mn0 * Cs, mc1 = mn1 * Cs;

        float rs0 = 0.0f, rs1 = 0.0f;
#pragma unroll
        for (int nf = 0; nf < 8; nf++) {
            s[nf][0] = ex2f(fmaf(s[nf][0], Cs, -mc0));
            s[nf][1] = ex2f(fmaf(s[nf][1], Cs, -mc0));
            s[nf][2] = ex2f(fmaf(s[nf][2], Cs, -mc1));
            s[nf][3] = ex2f(fmaf(s[nf][3], Cs, -mc1));
            rs0 += s[nf][0] + s[nf][1];
            rs1 += s[nf][2] + s[nf][3];
        }
        rs0 += __shfl_xor_sync(0xffffffffu, rs0, 1);
        rs0 += __shfl_xor_sync(0xffffffffu, rs0, 2);
        rs1 += __shfl_xor_sync(0xffffffffu, rs1, 1);
        rs1 += __shfl_xor_sync(0xffffffffu, rs1, 2);
        l0 = l0 * a0 + rs0;
        l1 = l1 * a1 + rs1;
#pragma unroll
        for (int nf = 0; nf < 8; nf++) {
            o[nf][0] *= a0; o[nf][1] *= a0;
            o[nf][2] *= a1; o[nf][3] *= a1;
        }

        // ---- P fragments (fp16) ----
        uint32_t pa[4][4];
#pragma unroll
        for (int kf = 0; kf < 4; kf++) {
            pa[kf][0] = f16pack(s[2 * kf][0],     s[2 * kf][1]);
            pa[kf][1] = f16pack(s[2 * kf][2],     s[2 * kf][3]);
            pa[kf][2] = f16pack(s[2 * kf + 1][0], s[2 * kf + 1][1]);
            pa[kf][3] = f16pack(s[2 * kf + 1][2], s[2 * kf + 1][3]);
        }

        // ---- O += P V (V single fp16) ----
#pragma unroll
        for (int kf = 0; kf < 4; kf++) {
#pragma unroll
            for (int np = 0; np < 4; np++) {
                const uint32_t addr = kb + V_P + (kf * 16 + vrow) * ROWF + (np * 16 + vcol) * 2;
                uint32_t v4[4];
                ldm_x4_t(v4, addr);
                mma_h(o[2 * np],     pa[kf], v4[0], v4[2]);
                mma_h(o[2 * np + 1], pa[kf], v4[1], v4[3]);
            }
        }
        __syncthreads();
    }

    // ---- epilogue: normalize, write fp16 hi/lo o ----
    const float inv0 = __fdividef(1.0f, l0);
    const float inv1 = __fdividef(1.0f, l1);
    const size_t gr0 = (bS + q0 + w * 16 + (lane >> 2)) * D_MODEL + h * DK;
    const size_t gr1 = gr0 + 8 * D_MODEL;
#pragma unroll
    for (int nf = 0; nf < 8; nf++) {
        const int c = nf * 8 + 2 * (lane & 3);
        float v0 = o[nf][0] * inv0, v1 = o[nf][1] * inv0;
        float v2 = o[nf][2] * inv1, v3 = o[nf][3] * inv1;
        __half h0 = __float2half_rn(v0), h1 = __float2half_rn(v1);
        __half h2 = __float2half_rn(v2), h3 = __float2half_rn(v3);
        __half e0 = __float2half_rn(v0 - __half2float(h0));
        __half e1 = __float2half_rn(v1 - __half2float(h1));
        __half e2 = __float2half_rn(v2 - __half2float(h2));
        __half e3 = __float2half_rn(v3 - __half2float(h3));
        *(uint32_t*)(g_oh + gr0 + c) = hpack(h0, h1);
        *(uint32_t*)(g_ol + gr0 + c) = hpack(e0, e1);
        *(uint32_t*)(g_oh + gr1 + c) = hpack(h2, h3);
        *(uint32_t*)(g_ol + gr1 + c) = hpack(e2, e3);
    }
}

// ==================== launch ====================
extern "C" void kernel_launch(void* const* d_in, const int* in_sizes, int n_in,
                              void* d_out, int out_size)
{
    const float* x  = (const float*)d_in[0];
    const float* Wq = (const float*)d_in[1];
    const float* bq = (const float*)d_in[2];
    const float* Wk = (const float*)d_in[3];
    const float* bk = (const float*)d_in[4];
    const float* Wv = (const float*)d_in[5];
    const float* bv = (const float*)d_in[6];
    const float* Wo = (const float*)d_in[7];
    const float* bo = (const float*)d_in[8];
    float* out = (float*)d_out;

    __half *xh, *xl, *oh, *ol, *qh, *ql, *kk, *vv;
    cudaGetSymbolAddress((void**)&xh, g_xh);
    cudaGetSymbolAddress((void**)&xl, g_xl);
    cudaGetSymbolAddress((void**)&oh, g_oh);
    cudaGetSymbolAddress((void**)&ol, g_ol);
    cudaGetSymbolAddress((void**)&qh, g_qh);
    cudaGetSymbolAddress((void**)&ql, g_ql);
    cudaGetSymbolAddress((void**)&kk, g_k);
    cudaGetSymbolAddress((void**)&vv, g_v);
    __half *wq, *wk, *wv, *wo;
    cudaGetSymbolAddress((void**)&wq, g_wqt);
    cudaGetSymbolAddress((void**)&wk, g_wkt);
    cudaGetSymbolAddress((void**)&wv, g_wvt);
    cudaGetSymbolAddress((void**)&wo, g_wot);

    cudaFuncSetAttribute((const void*)gemm2_kernel<0>,
                         cudaFuncAttributeMaxDynamicSharedMemorySize, GSMEM);
    cudaFuncSetAttribute((const void*)gemm2_kernel<1>,
                         cudaFuncAttributeMaxDynamicSharedMemorySize, GSMEM);
    cudaFuncSetAttribute((const void*)gemm2_kernel<2>,
                         cudaFuncAttributeMaxDynamicSharedMemorySize, GSMEM);
    cudaFuncSetAttribute((const void*)flash_mma_kernel,
                         cudaFuncAttributeMaxDynamicSharedMemorySize, FSMEM);

    // 1) split x; transpose weights to fp16
    const int n4 = MROWS * D_MODEL / 4;
    split_kernel<<<(n4 + 255) / 256, 256>>>(x, xh, xl, n4);
    dim3 tb(32, 8);
    transpose_h_kernel<<<dim3(D_MODEL / 32, D_MODEL / 32), tb>>>(Wq, wq, D_MODEL, D_MODEL);
    transpose_h_kernel<<<dim3(KV_DIM  / 32, D_MODEL / 32), tb>>>(Wk, wk, D_MODEL, KV_DIM);
    transpose_h_kernel<<<dim3(KV_DIM  / 32, D_MODEL / 32), tb>>>(Wv, wv, D_MODEL, KV_DIM);
    transpose_h_kernel<<<dim3(D_MODEL / 32, D_MODEL / 32), tb>>>(Wo, wo, D_MODEL, D_MODEL);

    // 2) projections: Q -> fp16 hi/lo; K,V -> fp16 single
    gemm2_kernel<1><<<dim3(D_MODEL / 128, MROWS / 128), 256, GSMEM>>>(
        xh, xl, wq, bq, nullptr, qh, ql, MROWS, D_MODEL, D_MODEL);
    gemm2_kernel<2><<<dim3(KV_DIM / 128, MROWS / 128), 256, GSMEM>>>(
        xh, xl, wk, bk, nullptr, kk, nullptr, MROWS, KV_DIM, D_MODEL);
    gemm2_kernel<2><<<dim3(KV_DIM / 128, MROWS / 128), 256, GSMEM>>>(
        xh, xl, wv, bv, nullptr, vv, nullptr, MROWS, KV_DIM, D_MODEL);

    // 3) flash attention -> fp16 hi/lo o
    flash_mma_kernel<<<dim3(SEQ / 64, N_HEADS, BATCH), 128, FSMEM>>>();

    // 4) output projection -> d_out (fp32)
    gemm2_kernel<0><<<dim3(D_MODEL / 128, MROWS / 128), 256, GSMEM>>>(
        oh, ol, wo, bo, out, nullptr, nullptr, MROWS, D_MODEL, D_MODEL);
}

// round 9
// speedup vs baseline: 6.5113x; 1.6697x over previous
#include <cuda_runtime.h>
#include <cuda_fp16.h>
#include <cstdint>

// ---------------------------------------------------------------------------
// GQA fp32 on mma.sync fp16 tensor cores, single-fp16 operands everywhere
// (error budget calibrated: ~5e-4 vs 1e-3 threshold). fp32 accumulators.
// ---------------------------------------------------------------------------

#define D_MODEL 2048
#define KV_DIM  512
#define N_HEADS 32
#define DK      64
#define BATCH   4
#define SEQ     2048
#define MROWS   (BATCH * SEQ)   // 8192

// ---- device scratch (allocation-free) ----
__device__ __half g_x [MROWS * D_MODEL];
__device__ __half g_q [MROWS * D_MODEL];
__device__ __half g_k [MROWS * KV_DIM];
__device__ __half g_v [MROWS * KV_DIM];
__device__ __half g_o [MROWS * D_MODEL];
__device__ __half g_wqt[D_MODEL * D_MODEL];
__device__ __half g_wkt[KV_DIM * D_MODEL];
__device__ __half g_wvt[KV_DIM * D_MODEL];
__device__ __half g_wot[D_MODEL * D_MODEL];

// ==================== helpers ====================
__device__ __forceinline__ uint32_t smem_u32(const void* p) {
    uint32_t a;
    asm("{ .reg .u64 t; cvta.to.shared.u64 t, %1; cvt.u32.u64 %0, t; }" : "=r"(a) : "l"(p));
    return a;
}
__device__ __forceinline__ void cp16(uint32_t dst, const void* src) {
    asm volatile("cp.async.cg.shared.global [%0], [%1], 16;" :: "r"(dst), "l"(src));
}
#define CP_COMMIT() asm volatile("cp.async.commit_group;" ::: "memory")
#define CP_WAIT(n)  asm volatile("cp.async.wait_group %0;" :: "n"(n) : "memory")

__device__ __forceinline__ void ldm_x4(uint32_t* r, uint32_t addr) {
    asm volatile("ldmatrix.sync.aligned.m8n8.x4.shared.b16 {%0,%1,%2,%3}, [%4];"
        : "=r"(r[0]), "=r"(r[1]), "=r"(r[2]), "=r"(r[3]) : "r"(addr) : "memory");
}
__device__ __forceinline__ void ldm_x4_t(uint32_t* r, uint32_t addr) {
    asm volatile("ldmatrix.sync.aligned.m8n8.x4.trans.shared.b16 {%0,%1,%2,%3}, [%4];"
        : "=r"(r[0]), "=r"(r[1]), "=r"(r[2]), "=r"(r[3]) : "r"(addr) : "memory");
}
__device__ __forceinline__ void ldm_x2(uint32_t* r, uint32_t addr) {
    asm volatile("ldmatrix.sync.aligned.m8n8.x2.shared.b16 {%0,%1}, [%2];"
        : "=r"(r[0]), "=r"(r[1]) : "r"(addr) : "memory");
}
__device__ __forceinline__ void mma_h(float* d, const uint32_t* a, uint32_t b0, uint32_t b1) {
    asm volatile("mma.sync.aligned.m16n8k16.row.col.f32.f16.f16.f32 "
        "{%0,%1,%2,%3}, {%4,%5,%6,%7}, {%8,%9}, {%0,%1,%2,%3};"
        : "+f"(d[0]), "+f"(d[1]), "+f"(d[2]), "+f"(d[3])
        : "r"(a[0]), "r"(a[1]), "r"(a[2]), "r"(a[3]), "r"(b0), "r"(b1));
}
__device__ __forceinline__ uint32_t f16pack(float lo, float hi) {
    uint32_t r;
    asm("cvt.rn.f16x2.f32 %0, %1, %2;" : "=r"(r) : "f"(hi), "f"(lo));
    return r;
}
__device__ __forceinline__ float ex2f(float x) {
    float y;
    asm("ex2.approx.f32 %0, %1;" : "=f"(y) : "f"(x));
    return y;
}
__device__ __forceinline__ uint32_t hpack(__half a, __half b) {
    return (uint32_t)__half_as_ushort(a) | ((uint32_t)__half_as_ushort(b) << 16);
}

// ==================== x convert: fp32 -> fp16 ====================
__global__ void __launch_bounds__(256)
convert_h_kernel(const float* __restrict__ X, __half* __restrict__ H, int n4)
{
    int i = blockIdx.x * 256 + threadIdx.x;
    if (i >= n4) return;
    float4 v = ((const float4*)X)[i];
    ((uint2*)H)[i] = make_uint2(f16pack(v.x, v.y), f16pack(v.z, v.w));
}

// ==================== weight transpose -> fp16 [N][K] ====================
__global__ void __launch_bounds__(256)
transpose_h_kernel(const float* __restrict__ W, __half* __restrict__ T, int Kd, int Nd)
{
    __shared__ float tile[32][33];
    const int tx = threadIdx.x, ty = threadIdx.y;
    const int n0 = blockIdx.x * 32, k0 = blockIdx.y * 32;
#pragma unroll
    for (int j = ty; j < 32; j += 8)
        tile[j][tx] = W[(size_t)(k0 + j) * Nd + n0 + tx];
    __syncthreads();
#pragma unroll
    for (int j = ty; j < 32; j += 8)
        T[(size_t)(n0 + j) * Kd + k0 + tx] = __float2half_rn(tile[tx][j]);
}

// ==================== single-fp16 GEMM ====================
// C[M,N] = A[M,K] @ B^T[N,K] + bias.  OUT=0: fp32 C.  OUT=1: fp16 Ch.
#define ROWB 80
#define TILEB (128 * ROWB)
#define STAGEB (2 * TILEB)            // A, B
#define GSMEM (2 * STAGEB)            // 40960

template <int OUT>
__global__ void __launch_bounds__(256, 2)
gemm1_kernel(const __half* __restrict__ A, const __half* __restrict__ B,
             const float* __restrict__ bias, float* __restrict__ C,
             __half* __restrict__ Ch, int M, int N, int K)
{
    extern __shared__ __align__(16) char smem[];
    const uint32_t sb = smem_u32(smem);
    const int tid = threadIdx.x;
    const int lane = tid & 31, w = tid >> 5;
    const int wr = w >> 2, wc = w & 3;
    const int row0 = blockIdx.y * 128, col0 = blockIdx.x * 128;
    const int nc = K >> 5;

    const __half* srcs[2] = { A + (size_t)row0 * K, B + (size_t)col0 * K };

    auto load_stage = [&](int kc, int st) {
        uint32_t stb = sb + st * STAGEB;
#pragma unroll
        for (int arr = 0; arr < 2; arr++) {
            const __half* s = srcs[arr];
            uint32_t base = stb + arr * TILEB;
#pragma unroll
            for (int i = 0; i < 2; i++) {
                int chunk = tid + i * 256;
                int r = chunk >> 2, kq = chunk & 3;
                cp16(base + r * ROWB + kq * 16,
                     s + (size_t)r * K + kc * 32 + kq * 8);
            }
        }
    };

    float d[4][4][4];
#pragma unroll
    for (int mf = 0; mf < 4; mf++)
#pragma unroll
        for (int nf = 0; nf < 4; nf++)
#pragma unroll
            for (int e = 0; e < 4; e++) d[mf][nf][e] = 0.0f;

    load_stage(0, 0);
    CP_COMMIT();

    const uint32_t a_lane_off = (lane & 15) * ROWB + (lane >> 4) * 16;
    const uint32_t b_lane_off = (lane & 7) * ROWB + ((lane >> 3) & 1) * 16;

    for (int kc = 0; kc < nc; kc++) {
        const int st = kc & 1;
        if (kc + 1 < nc) { load_stage(kc + 1, st ^ 1); CP_COMMIT(); CP_WAIT(1); }
        else            { CP_WAIT(0); }
        __syncthreads();

        const uint32_t aA = sb + st * STAGEB + 0 * TILEB + wr * 64 * ROWB + a_lane_off;
        const uint32_t bB = sb + st * STAGEB + 1 * TILEB + wc * 32 * ROWB + b_lane_off;

#pragma unroll
        for (int ks = 0; ks < 2; ks++) {
            const uint32_t ko = ks * 32;
            uint32_t ah[4][4], bh[4][2];
#pragma unroll
            for (int mf = 0; mf < 4; mf++)
                ldm_x4(ah[mf], aA + mf * 16 * ROWB + ko);
#pragma unroll
            for (int nf = 0; nf < 4; nf++)
                ldm_x2(bh[nf], bB + nf * 8 * ROWB + ko);
#pragma unroll
            for (int mf = 0; mf < 4; mf++)
#pragma unroll
                for (int nf = 0; nf < 4; nf++)
                    mma_h(d[mf][nf], ah[mf], bh[nf][0], bh[nf][1]);
        }
        __syncthreads();
    }

#pragma unroll
    for (int mf = 0; mf < 4; mf++) {
        const int r = row0 + wr * 64 + mf * 16 + (lane >> 2);
#pragma unroll
        for (int nf = 0; nf < 4; nf++) {
            const int c = col0 + wc * 32 + nf * 8 + (lane & 3) * 2;
            const float b0 = bias[c], b1 = bias[c + 1];
            float v00 = d[mf][nf][0] + b0, v01 = d[mf][nf][1] + b1;
            float v10 = d[mf][nf][2] + b0, v11 = d[mf][nf][3] + b1;
            if (OUT == 0) {
                *(float2*)(C + (size_t)r * N + c) = make_float2(v00, v01);
                *(float2*)(C + (size_t)(r + 8) * N + c) = make_float2(v10, v11);
            } else {
                *(uint32_t*)(Ch + (size_t)r * N + c)       = f16pack(v00, v01);
                *(uint32_t*)(Ch + (size_t)(r + 8) * N + c) = f16pack(v10, v11);
            }
        }
    }
}

// ==================== flash attention (single fp16 operands) ====================
// 128 threads / 4 warps; BR=BC=64, DK=64. S = Q*K (1 MMA); PV = P*V (1 MMA).
#define ROWF 144
#define Q_OFF 0
#define STG_OFF (64 * ROWF)            // 9216
#define K_P 0
#define V_P (64 * ROWF)
#define STG_SZ (2 * 64 * ROWF)         // 18432
#define FSMEM (STG_OFF + 2 * STG_SZ)   // 46080

__global__ void __launch_bounds__(128, 2)
flash_mma_kernel()
{
    extern __shared__ __align__(16) char fsm[];
    const uint32_t sb = smem_u32(fsm);
    const int tid = threadIdx.x;
    const int lane = tid & 31, w = tid >> 5;
    const int b = blockIdx.z, h = blockIdx.y;
    const int qi = (int)gridDim.x - 1 - (int)blockIdx.x;
    const int q0 = qi * 64;
    const int kvh = h >> 2;
    const size_t bS = (size_t)b * SEQ;

    const __half* qp = g_q + (bS + q0) * D_MODEL + h * DK;
    const __half* kp = g_k + bS * KV_DIM + kvh * DK;
    const __half* vp = g_v + bS * KV_DIM + kvh * DK;

    auto load_kv = [&](int t, int st) {
        uint32_t base = sb + STG_OFF + st * STG_SZ;
        const size_t g0 = (size_t)(t * 64);
#pragma unroll
        for (int i = 0; i < 4; i++) {
            int ch = tid + i * 128;
            int r = ch >> 3, off = ch & 7;
            size_t g = (g0 + r) * KV_DIM + off * 8;
            uint32_t so = r * ROWF + off * 16;
            cp16(base + K_P + so, kp + g);
            cp16(base + V_P + so, vp + g);
        }
    };

#pragma unroll
    for (int i = 0; i < 4; i++) {
        int ch = tid + i * 128;
        int r = ch >> 3, off = ch & 7;
        cp16(sb + Q_OFF + r * ROWF + off * 16, qp + (size_t)r * D_MODEL + off * 8);
    }
    CP_COMMIT();
    load_kv(0, 0);
    CP_COMMIT();
    CP_WAIT(0);
    __syncthreads();

    uint32_t qf[4][4];
    {
        const uint32_t aoff = (uint32_t)((w * 16 + (lane & 15)) * ROWF + (lane >> 4) * 16);
#pragma unroll
        for (int kf = 0; kf < 4; kf++)
            ldm_x4(qf[kf], sb + Q_OFF + aoff + kf * 32);
    }

    float o[8][4];
#pragma unroll
    for (int nf = 0; nf < 8; nf++)
#pragma unroll
        for (int e = 0; e < 4; e++) o[nf][e] = 0.0f;
    float m0 = -1e30f, m1 = -1e30f, l0 = 0.0f, l1 = 0.0f;
    const float Cs = 0.18033688011112042f;   // (1/8) * log2(e)

    const uint32_t krow = ((((lane >> 3) & 1) * 8 + (lane & 7))) * ROWF;
    const uint32_t kcol = ((lane >> 4) & 1) * 16;
    const uint32_t vrow = (((lane >> 4) & 1) * 8 + (lane & 7));
    const uint32_t vcol = (((lane >> 3) & 1) * 8);

    for (int t = 0; t <= qi; t++) {
        const int st = t & 1;
        if (t < qi) { load_kv(t + 1, st ^ 1); CP_COMMIT(); CP_WAIT(1); }
        else        { CP_WAIT(0); }
        __syncthreads();
        const uint32_t kb = sb + STG_OFF + st * STG_SZ;

        // ---- S = Q K^T (single fp16: 1 MMA per fragment) ----
        float s[8][4];
#pragma unroll
        for (int nf = 0; nf < 8; nf++)
#pragma unroll
            for (int e = 0; e < 4; e++) s[nf][e] = 0.0f;

#pragma unroll
        for (int kf = 0; kf < 4; kf++) {
#pragma unroll
            for (int np = 0; np < 4; np++) {
                const uint32_t addr = kb + K_P + np * (16 * ROWF) + krow + kf * 32 + kcol;
                uint32_t k4[4];
                ldm_x4(k4, addr);
                mma_h(s[2 * np],     qf[kf], k4[0], k4[2]);
                mma_h(s[2 * np + 1], qf[kf], k4[1], k4[3]);
            }
        }

        if (t == qi) {
            const int r0 = w * 16 + (lane >> 2);
            const int cb = 2 * (lane & 3);
#pragma unroll
            for (int nf = 0; nf < 8; nf++) {
                int c0 = nf * 8 + cb;
                if (c0     > r0)     s[nf][0] = -1e30f;
                if (c0 + 1 > r0)     s[nf][1] = -1e30f;
                if (c0     > r0 + 8) s[nf][2] = -1e30f;
                if (c0 + 1 > r0 + 8) s[nf][3] = -1e30f;
            }
        }

        // ---- online softmax ----
        float mx0 = s[0][0], mx1 = s[0][2];
#pragma unroll
        for (int nf = 0; nf < 8; nf++) {
            mx0 = fmaxf(mx0, fmaxf(s[nf][0], s[nf][1]));
            mx1 = fmaxf(mx1, fmaxf(s[nf][2], s[nf][3]));
        }
        mx0 = fmaxf(mx0, __shfl_xor_sync(0xffffffffu, mx0, 1));
        mx0 = fmaxf(mx0, __shfl_xor_sync(0xffffffffu, mx0, 2));
        mx1 = fmaxf(mx1, __shfl_xor_sync(0xffffffffu, mx1, 1));
        mx1 = fmaxf(mx1, __shfl_xor_sync(0xffffffffu, mx1, 2));
        const float mn0 = fmaxf(m0, mx0), mn1 = fmaxf(m1, mx1);
        const float a0 = ex2f((m0 - mn0) * Cs);
        const float a1 = ex2f((m1 - mn1) * Cs);
        m0 = mn0; m1 = mn1;
        const float mc0 = mn0 * Cs, mc1 = mn1 * Cs;

        float rs0 = 0.0f, rs1 = 0.0f;
#pragma unroll
        for (int nf = 0; nf < 8; nf++) {
            s[nf][0] = ex2f(fmaf(s[nf][0], Cs, -mc0));
            s[nf][1] = ex2f(fmaf(s[nf][1], Cs, -mc0));
            s[nf][2] = ex2f(fmaf(s[nf][2], Cs, -mc1));
            s[nf][3] = ex2f(fmaf(s[nf][3], Cs, -mc1));
            rs0 += s[nf][0] + s[nf][1];
            rs1 += s[nf][2] + s[nf][3];
        }
        rs0 += __shfl_xor_sync(0xffffffffu, rs0, 1);
        rs0 += __shfl_xor_sync(0xffffffffu, rs0, 2);
        rs1 += __shfl_xor_sync(0xffffffffu, rs1, 1);
        rs1 += __shfl_xor_sync(0xffffffffu, rs1, 2);
        l0 = l0 * a0 + rs0;
        l1 = l1 * a1 + rs1;
#pragma unroll
        for (int nf = 0; nf < 8; nf++) {
            o[nf][0] *= a0; o[nf][1] *= a0;
            o[nf][2] *= a1; o[nf][3] *= a1;
        }

        // ---- P fragments (fp16) ----
        uint32_t pa[4][4];
#pragma unroll
        for (int kf = 0; kf < 4; kf++) {
            pa[kf][0] = f16pack(s[2 * kf][0],     s[2 * kf][1]);
            pa[kf][1] = f16pack(s[2 * kf][2],     s[2 * kf][3]);
            pa[kf][2] = f16pack(s[2 * kf + 1][0], s[2 * kf + 1][1]);
            pa[kf][3] = f16pack(s[2 * kf + 1][2], s[2 * kf + 1][3]);
        }

        // ---- O += P V ----
#pragma unroll
        for (int kf = 0; kf < 4; kf++) {
#pragma unroll
            for (int np = 0; np < 4; np++) {
                const uint32_t addr = kb + V_P + (kf * 16 + vrow) * ROWF + (np * 16 + vcol) * 2;
                uint32_t v4[4];
                ldm_x4_t(v4, addr);
                mma_h(o[2 * np],     pa[kf], v4[0], v4[2]);
                mma_h(o[2 * np + 1], pa[kf], v4[1], v4[3]);
            }
        }
        __syncthreads();
    }

    // ---- epilogue: normalize, write fp16 o ----
    const float inv0 = __fdividef(1.0f, l0);
    const float inv1 = __fdividef(1.0f, l1);
    const size_t gr0 = (bS + q0 + w * 16 + (lane >> 2)) * D_MODEL + h * DK;
    const size_t gr1 = gr0 + 8 * D_MODEL;
#pragma unroll
    for (int nf = 0; nf < 8; nf++) {
        const int c = nf * 8 + 2 * (lane & 3);
        *(uint32_t*)(g_o + gr0 + c) = f16pack(o[nf][0] * inv0, o[nf][1] * inv0);
        *(uint32_t*)(g_o + gr1 + c) = f16pack(o[nf][2] * inv1, o[nf][3] * inv1);
    }
}

// ==================== launch ====================
extern "C" void kernel_launch(void* const* d_in, const int* in_sizes, int n_in,
                              void* d_out, int out_size)
{
    const float* x  = (const float*)d_in[0];
    const float* Wq = (const float*)d_in[1];
    const float* bq = (const float*)d_in[2];
    const float* Wk = (const float*)d_in[3];
    const float* bk = (const float*)d_in[4];
    const float* Wv = (const float*)d_in[5];
    const float* bv = (const float*)d_in[6];
    const float* Wo = (const float*)d_in[7];
    const float* bo = (const float*)d_in[8];
    float* out = (float*)d_out;

    __half *xp, *qp, *kp, *vp, *op, *wq, *wk, *wv, *wo;
    cudaGetSymbolAddress((void**)&xp, g_x);
    cudaGetSymbolAddress((void**)&qp, g_q);
    cudaGetSymbolAddress((void**)&kp, g_k);
    cudaGetSymbolAddress((void**)&vp, g_v);
    cudaGetSymbolAddress((void**)&op, g_o);
    cudaGetSymbolAddress((void**)&wq, g_wqt);
    cudaGetSymbolAddress((void**)&wk, g_wkt);
    cudaGetSymbolAddress((void**)&wv, g_wvt);
    cudaGetSymbolAddress((void**)&wo, g_wot);

    cudaFuncSetAttribute((const void*)gemm1_kernel<0>,
                         cudaFuncAttributeMaxDynamicSharedMemorySize, GSMEM);
    cudaFuncSetAttribute((const void*)gemm1_kernel<1>,
                         cudaFuncAttributeMaxDynamicSharedMemorySize, GSMEM);
    cudaFuncSetAttribute((const void*)flash_mma_kernel,
                         cudaFuncAttributeMaxDynamicSharedMemorySize, FSMEM);

    // 1) convert x; transpose weights to fp16
    const int n4 = MROWS * D_MODEL / 4;
    convert_h_kernel<<<(n4 + 255) / 256, 256>>>(x, xp, n4);
    dim3 tb(32, 8);
    transpose_h_kernel<<<dim3(D_MODEL / 32, D_MODEL / 32), tb>>>(Wq, wq, D_MODEL, D_MODEL);
    transpose_h_kernel<<<dim3(KV_DIM  / 32, D_MODEL / 32), tb>>>(Wk, wk, D_MODEL, KV_DIM);
    transpose_h_kernel<<<dim3(KV_DIM  / 32, D_MODEL / 32), tb>>>(Wv, wv, D_MODEL, KV_DIM);
    transpose_h_kernel<<<dim3(D_MODEL / 32, D_MODEL / 32), tb>>>(Wo, wo, D_MODEL, D_MODEL);

    // 2) projections -> fp16 q, k, v
    gemm1_kernel<1><<<dim3(D_MODEL / 128, MROWS / 128), 256, GSMEM>>>(
        xp, wq, bq, nullptr, qp, MROWS, D_MODEL, D_MODEL);
    gemm1_kernel<1><<<dim3(KV_DIM / 128, MROWS / 128), 256, GSMEM>>>(
        xp, wk, bk, nullptr, kp, MROWS, KV_DIM, D_MODEL);
    gemm1_kernel<1><<<dim3(KV_DIM / 128, MROWS / 128), 256, GSMEM>>>(
        xp, wv, bv, nullptr, vp, MROWS, KV_DIM, D_MODEL);

    // 3) flash attention -> fp16 o
    flash_mma_kernel<<<dim3(SEQ / 64, N_HEADS, BATCH), 128, FSMEM>>>();

    // 4) output projection -> d_out (fp32)
    gemm1_kernel<0><<<dim3(D_MODEL / 128, MROWS / 128), 256, GSMEM>>>(
        op, wo, bo, out, nullptr, MROWS, D_MODEL, D_MODEL);
}